// round 4
// baseline (speedup 1.0000x reference)
#include <cuda_runtime.h>
#include <math.h>

typedef unsigned long long ull;

#define NPTS 16384
#define KNB 32
#define CCH 64
#define PPB 4          // points per block
#define NTHREADS 256
#define H1S 68         // h1 row stride: 8B/16B aligned, decent bank spread
#define EPSF 1e-5f

// ---- packed fp32x2 helpers (Blackwell dual fp32 pipes; FFMA2 only via PTX) ----
__device__ __forceinline__ void fma2(ull& d, ull a, ull b) {
  asm("fma.rn.f32x2 %0, %1, %2, %0;" : "+l"(d) : "l"(a), "l"(b));
}
__device__ __forceinline__ ull pack2(float lo, float hi) {
  ull r; asm("mov.b64 %0, {%1, %2};" : "=l"(r) : "f"(lo), "f"(hi)); return r;
}
__device__ __forceinline__ float2 unpack2(ull v) {
  float2 r; asm("mov.b64 {%0, %1}, %2;" : "=f"(r.x), "=f"(r.y) : "l"(v)); return r;
}

struct Smem {
  float Wp[CCH][12];        // [c][0..9]=a1*W_pos, [10]=folded bias1, [11]=0   (3 KB)
  float WgI[32][8][20];     // [cp][dt][(d&7)*2+par] = a2[d]*W_gcm[d][2cp+par] (20 KB, stride-20: conflict-free)
  float a1s[CCH], a2s[CCH], bias2[CCH];
  float Watt[KNB];
  float h1[PPB][KNB * H1S]; // 34 KB
  float ps[PPB][2][CCH];    // per-warp attention partials
  float pm[PPB][2][CCH];    // per-warp max partials
  float resv[PPB][CCH];
  float redA[PPB][2], redB[PPB][2], redC[PPB][2], redD[PPB][2];
};

__global__ __launch_bounds__(NTHREADS, 2)
void bridgenet_kernel(
    const float* __restrict__ points,
    const float* __restrict__ features,
    const int*   __restrict__ gidx,
    const float* __restrict__ W_pos,
    const float* __restrict__ b_pos,
    const float* __restrict__ bn1_g, const float* __restrict__ bn1_b,
    const float* __restrict__ bn1_m, const float* __restrict__ bn1_v,
    const float* __restrict__ W_gcm,
    const float* __restrict__ b_gcm,
    const float* __restrict__ bn2_g, const float* __restrict__ bn2_b,
    const float* __restrict__ bn2_m, const float* __restrict__ bn2_v,
    const float* __restrict__ W_att,
    const float* __restrict__ W_out,
    const float* __restrict__ b_out,
    const float* __restrict__ ln_g, const float* __restrict__ ln_b,
    float* __restrict__ out)
{
  extern __shared__ char smem_raw[];
  Smem& s = *reinterpret_cast<Smem*>(smem_raw);
  const int tid = threadIdx.x;

  // ---------------- Weight prep: BN folding + layouts ----------------
  if (tid < CCH) {
    float a1 = bn1_g[tid] * rsqrtf(bn1_v[tid] + EPSF);
    s.a1s[tid] = a1;
    s.Wp[tid][10] = a1 * (b_pos[tid] - bn1_m[tid]) + bn1_b[tid];
    s.Wp[tid][11] = 0.0f;
    float a2 = bn2_g[tid] * rsqrtf(bn2_v[tid] + EPSF);
    s.a2s[tid] = a2;
    s.bias2[tid] = a2 * (b_gcm[tid] - bn2_m[tid]) + bn2_b[tid];
  }
  if (tid >= CCH && tid < CCH + KNB) s.Watt[tid - CCH] = W_att[tid - CCH];
  __syncthreads();

  for (int i = tid; i < CCH * 10; i += NTHREADS) {
    int c = i / 10, g = i - c * 10;
    s.Wp[c][g] = s.a1s[c] * W_pos[i];
  }
  for (int i = tid; i < CCH * CCH; i += NTHREADS) {
    int d = i >> 6, c = i & 63;
    s.WgI[c >> 1][d >> 3][(d & 7) * 2 + (c & 1)] = s.a2s[d] * W_gcm[d * CCH + c];
  }
  __syncthreads();

  const int pt = tid >> 6;           // point within block
  const int tp = tid & 63;           // thread within point
  const int wip = tp >> 5;           // warp within point
  const int p  = blockIdx.x * PPB + pt;
  const int bb = p >> 14;            // N = 16384
  const int nn = p & (NPTS - 1);
  const int base_pn = bb * NPTS + nn;

  // ---------------- Phase 1: gather + pos-encoding -> h1 (packed f32x2) ----
  {
    const int k    = tp >> 1;
    const int half = tp & 1;
    const int coff = half * 32;
    const int idx  = gidx[base_pn * KNB + k];
    const int gb   = bb * NPTS + idx;

    const float xix = points[base_pn * 3 + 0];
    const float xiy = points[base_pn * 3 + 1];
    const float xiz = points[base_pn * 3 + 2];
    const float gx  = points[gb * 3 + 0];
    const float gy  = points[gb * 3 + 1];
    const float gz  = points[gb * 3 + 2];
    const float dx = xix - gx, dy = xiy - gy, dz = xiz - gz;
    const float dist = sqrtf(dx*dx + dy*dy + dz*dz);

    ull gp[6];
    gp[0] = pack2(xix, xiy);
    gp[1] = pack2(xiz, gx);
    gp[2] = pack2(gy,  gz);
    gp[3] = pack2(dx,  dy);
    gp[4] = pack2(dz,  dist);
    gp[5] = pack2(1.0f, 0.0f);       // picks up (bias1, 0) from Wp[c][10..11]

    const float4* fp4 = reinterpret_cast<const float4*>(features + gb * CCH + coff);
    float4 f[8];
    #pragma unroll
    for (int j = 0; j < 8; ++j) f[j] = fp4[j];

    float* h1row = &s.h1[pt][k * H1S + coff];
    #pragma unroll
    for (int jj = 0; jj < 8; ++jj) {
      float4 res;
      float fv[4] = {f[jj].x, f[jj].y, f[jj].z, f[jj].w};
      float* rp = (float*)&res;
      #pragma unroll
      for (int q = 0; q < 4; ++q) {
        const int c = coff + jj * 4 + q;
        const ulonglong2* wrow = reinterpret_cast<const ulonglong2*>(&s.Wp[c][0]);
        ulonglong2 wa = wrow[0], wb = wrow[1], wc = wrow[2];
        ull e2 = 0ULL;                       // (0.0f, 0.0f)
        fma2(e2, gp[0], wa.x);
        fma2(e2, gp[1], wa.y);
        fma2(e2, gp[2], wb.x);
        fma2(e2, gp[3], wb.y);
        fma2(e2, gp[4], wc.x);
        fma2(e2, gp[5], wc.y);               // + bias1
        float2 e = unpack2(e2);
        rp[q] = fmaxf(e.x + e.y, 0.0f) + fv[q];
      }
      *reinterpret_cast<float4*>(&h1row[jj * 4]) = res;
    }
  }
  __syncthreads();

  // ---------------- Phase 2: h2 GEMM via f32x2 (pairs over c-parity) -------
  {
    const int dt = tp & 7;           // 8 d-cols each; low bits -> conflict-free W reads
    const int kt = tp >> 3;          // 4 k-rows each
    const float* h1p = &s.h1[pt][kt * 4 * H1S];

    ull acc[4][8];
    #pragma unroll
    for (int kk = 0; kk < 4; ++kk)
      #pragma unroll
      for (int j = 0; j < 8; ++j) acc[kk][j] = 0ULL;

    #pragma unroll 2
    for (int cp = 0; cp < 32; ++cp) {
      ull hp[4];
      #pragma unroll
      for (int kk = 0; kk < 4; ++kk)
        hp[kk] = *reinterpret_cast<const ull*>(&h1p[kk * H1S + 2 * cp]);

      const ulonglong2* wb = reinterpret_cast<const ulonglong2*>(&s.WgI[cp][dt][0]);
      ulonglong2 w0 = wb[0], w1 = wb[1], w2 = wb[2], w3 = wb[3];
      ull wp[8] = {w0.x, w0.y, w1.x, w1.y, w2.x, w2.y, w3.x, w3.y};

      #pragma unroll
      for (int kk = 0; kk < 4; ++kk)
        #pragma unroll
        for (int j = 0; j < 8; ++j)
          fma2(acc[kk][j], hp[kk], wp[j]);
    }

    const float wa0 = s.Watt[kt * 4 + 0];
    const float wa1 = s.Watt[kt * 4 + 1];
    const float wa2 = s.Watt[kt * 4 + 2];
    const float wa3 = s.Watt[kt * 4 + 3];

    float sp[8], mp[8];
    #pragma unroll
    for (int j = 0; j < 8; ++j) {
      const float b2 = s.bias2[dt * 8 + j];
      float2 t0 = unpack2(acc[0][j]);
      float2 t1 = unpack2(acc[1][j]);
      float2 t2 = unpack2(acc[2][j]);
      float2 t3 = unpack2(acc[3][j]);
      const float h20 = fmaxf(t0.x + t0.y + b2, 0.0f);
      const float h21 = fmaxf(t1.x + t1.y + b2, 0.0f);
      const float h22 = fmaxf(t2.x + t2.y + b2, 0.0f);
      const float h23 = fmaxf(t3.x + t3.y + b2, 0.0f);
      sp[j] = h20 * wa0 + h21 * wa1 + h22 * wa2 + h23 * wa3;
      mp[j] = fmaxf(fmaxf(h20, h21), fmaxf(h22, h23));   // h2 >= 0
    }

    // reduce over kt: lane bits 3,4 within warp; cross-warp half via SMEM
    #pragma unroll
    for (int m = 8; m <= 16; m <<= 1) {
      #pragma unroll
      for (int j = 0; j < 8; ++j) {
        sp[j] += __shfl_xor_sync(0xffffffffu, sp[j], m);
        mp[j]  = fmaxf(mp[j], __shfl_xor_sync(0xffffffffu, mp[j], m));
      }
    }
    if ((tp & 24) == 0) {
      #pragma unroll
      for (int j = 0; j < 8; ++j) {
        s.ps[pt][wip][dt * 8 + j] = sp[j];
        s.pm[pt][wip][dt * 8 + j] = mp[j];
      }
    }
  }
  __syncthreads();

  // ---------------- Phase 3: softmax over C, pool, residual ----------------
  {
    const int c = tp;
    const float sv = s.ps[pt][0][c] + s.ps[pt][1][c];   // b_att softmax-invariant
    const float mv = fmaxf(s.pm[pt][0][c], s.pm[pt][1][c]);

    float mx = sv;
    #pragma unroll
    for (int m = 16; m >= 1; m >>= 1)
      mx = fmaxf(mx, __shfl_xor_sync(0xffffffffu, mx, m));
    if ((tp & 31) == 0) s.redA[pt][wip] = mx;
    __syncthreads();
    mx = fmaxf(s.redA[pt][0], s.redA[pt][1]);

    const float e = expf(sv - mx);
    float se = e;
    #pragma unroll
    for (int m = 16; m >= 1; m >>= 1)
      se += __shfl_xor_sync(0xffffffffu, se, m);
    if ((tp & 31) == 0) s.redB[pt][wip] = se;
    __syncthreads();
    se = s.redB[pt][0] + s.redB[pt][1];

    const float score = e / se;
    s.resv[pt][c] = score * mv + features[base_pn * CCH + c];  // pooled + residual
  }
  __syncthreads();

  // ---------------- Phase 4: out GEMM (f32x2) + LayerNorm + ReLU -----------
  {
    const int o = tp;
    const ulonglong2* wrow = reinterpret_cast<const ulonglong2*>(W_out + o * CCH);
    ull e2 = 0ULL;
    #pragma unroll
    for (int q = 0; q < 16; ++q) {
      ulonglong2 w = wrow[q];                                            // LDG.128 (L1-resident)
      ulonglong2 r = *reinterpret_cast<const ulonglong2*>(&s.resv[pt][q * 4]); // broadcast LDS
      fma2(e2, r.x, w.x);
      fma2(e2, r.y, w.y);
    }
    float2 ee = unpack2(e2);
    float acc = ee.x + ee.y + b_out[o];

    float sum = acc, sq = acc * acc;
    #pragma unroll
    for (int m = 16; m >= 1; m >>= 1) {
      sum += __shfl_xor_sync(0xffffffffu, sum, m);
      sq  += __shfl_xor_sync(0xffffffffu, sq, m);
    }
    if ((tp & 31) == 0) { s.redC[pt][wip] = sum; s.redD[pt][wip] = sq; }
    __syncthreads();
    sum = s.redC[pt][0] + s.redC[pt][1];
    sq  = s.redD[pt][0] + s.redD[pt][1];

    const float mu  = sum * (1.0f / 64.0f);
    const float var = sq * (1.0f / 64.0f) - mu * mu;
    const float r   = rsqrtf(var + EPSF);
    const float y   = ln_g[o] * (acc - mu) * r + ln_b[o];
    out[base_pn * CCH + o] = fmaxf(y, 0.0f);
  }
}

extern "C" void kernel_launch(void* const* d_in, const int* in_sizes, int n_in,
                              void* d_out, int out_size) {
  const float* points   = (const float*)d_in[0];
  const float* features = (const float*)d_in[1];
  const int*   gidx     = (const int*)  d_in[2];
  const float* W_pos    = (const float*)d_in[3];
  const float* b_pos    = (const float*)d_in[4];
  const float* bn1_g    = (const float*)d_in[5];
  const float* bn1_b    = (const float*)d_in[6];
  const float* bn1_m    = (const float*)d_in[7];
  const float* bn1_v    = (const float*)d_in[8];
  const float* W_gcm    = (const float*)d_in[9];
  const float* b_gcm    = (const float*)d_in[10];
  const float* bn2_g    = (const float*)d_in[11];
  const float* bn2_b    = (const float*)d_in[12];
  const float* bn2_m    = (const float*)d_in[13];
  const float* bn2_v    = (const float*)d_in[14];
  const float* W_att    = (const float*)d_in[15];
  // d_in[16] = b_att (scalar): softmax-invariant, unused.
  const float* W_out    = (const float*)d_in[17];
  const float* b_out    = (const float*)d_in[18];
  const float* ln_g     = (const float*)d_in[19];
  const float* ln_b     = (const float*)d_in[20];
  float* out = (float*)d_out;

  const size_t smem = sizeof(Smem);
  cudaFuncSetAttribute((const void*)bridgenet_kernel,
                       cudaFuncAttributeMaxDynamicSharedMemorySize, (int)smem);

  const int total_pts = 2 * NPTS;             // 32768
  dim3 grid(total_pts / PPB);                 // 8192 blocks
  bridgenet_kernel<<<grid, NTHREADS, smem>>>(
      points, features, gidx, W_pos, b_pos,
      bn1_g, bn1_b, bn1_m, bn1_v,
      W_gcm, b_gcm, bn2_g, bn2_b, bn2_m, bn2_v,
      W_att, W_out, b_out, ln_g, ln_b, out);
}

// round 6
// speedup vs baseline: 1.1021x; 1.1021x over previous
#include <cuda_runtime.h>
#include <math.h>

typedef unsigned long long ull;

#define NPTS 16384
#define KNB 32
#define CCH 64
#define PPB 4          // points per block
#define NTHREADS 256
#define H1S 68         // h1 row stride (floats): float4-aligned
#define WGS 68         // Wg2 row stride
#define EPSF 1e-5f

// ---- packed fp32x2 helpers (FFMA2 only reachable via PTX) ----
__device__ __forceinline__ void fma2(ull& d, ull a, ull b) {
  asm("fma.rn.f32x2 %0, %1, %2, %0;" : "+l"(d) : "l"(a), "l"(b));
}
__device__ __forceinline__ ull pack2(float lo, float hi) {
  ull r; asm("mov.b64 %0, {%1, %2};" : "=l"(r) : "f"(lo), "f"(hi)); return r;
}
__device__ __forceinline__ float2 unpack2(ull v) {
  float2 r; asm("mov.b64 {%0, %1}, %2;" : "=f"(r.x), "=f"(r.y) : "l"(v)); return r;
}

struct Smem {
  float Wp[CCH][12];         // [c][0..9]=a1*W_pos, [10]=folded bias1, [11]=0
  float Wg2[CCH][WGS];       // [c][d] = a2[d]*W_gcm[d][c]
  float a1s[CCH], a2s[CCH], bias2[CCH];
  float Watt[KNB];
  float h1[PPB][KNB * H1S];
  float ps[PPB][2][CCH];     // per-warp attention partials
  float pm[PPB][2][CCH];     // per-warp max partials
  float resv[PPB][CCH];
  float redA[PPB][2], redB[PPB][2], redC[PPB][2], redD[PPB][2];
};

__global__ __launch_bounds__(NTHREADS, 3)
void bridgenet_kernel(
    const float* __restrict__ points,
    const float* __restrict__ features,
    const int*   __restrict__ gidx,
    const float* __restrict__ W_pos,
    const float* __restrict__ b_pos,
    const float* __restrict__ bn1_g, const float* __restrict__ bn1_b,
    const float* __restrict__ bn1_m, const float* __restrict__ bn1_v,
    const float* __restrict__ W_gcm,
    const float* __restrict__ b_gcm,
    const float* __restrict__ bn2_g, const float* __restrict__ bn2_b,
    const float* __restrict__ bn2_m, const float* __restrict__ bn2_v,
    const float* __restrict__ W_att,
    const float* __restrict__ W_out,
    const float* __restrict__ b_out,
    const float* __restrict__ ln_g, const float* __restrict__ ln_b,
    float* __restrict__ out)
{
  extern __shared__ char smem_raw[];
  Smem& s = *reinterpret_cast<Smem*>(smem_raw);
  const int tid = threadIdx.x;

  // ---------------- Weight prep: BN folding + layouts ----------------
  if (tid < CCH) {
    float a1 = bn1_g[tid] * rsqrtf(bn1_v[tid] + EPSF);
    s.a1s[tid] = a1;
    s.Wp[tid][10] = a1 * (b_pos[tid] - bn1_m[tid]) + bn1_b[tid];
    s.Wp[tid][11] = 0.0f;
    float a2 = bn2_g[tid] * rsqrtf(bn2_v[tid] + EPSF);
    s.a2s[tid] = a2;
    s.bias2[tid] = a2 * (b_gcm[tid] - bn2_m[tid]) + bn2_b[tid];
  }
  if (tid >= CCH && tid < CCH + KNB) s.Watt[tid - CCH] = W_att[tid - CCH];
  __syncthreads();

  for (int i = tid; i < CCH * 10; i += NTHREADS) {
    int c = i / 10, g = i - c * 10;
    s.Wp[c][g] = s.a1s[c] * W_pos[i];
  }
  for (int i = tid; i < CCH * CCH; i += NTHREADS) {
    int d = i >> 6, c = i & 63;
    s.Wg2[c][d] = s.a2s[d] * W_gcm[i];     // W_gcm[d][c]
  }
  __syncthreads();

  const int pt = tid >> 6;           // point within block
  const int tp = tid & 63;           // thread within point
  const int wip = tp >> 5;           // warp within point
  const int p  = blockIdx.x * PPB + pt;
  const int bb = p >> 14;            // N = 16384
  const int nn = p & (NPTS - 1);
  const int base_pn = bb * NPTS + nn;

  // ---------------- Phase 1: gather + pos-encoding -> h1 ----
  {
    const int k    = tp >> 1;
    const int half = tp & 1;
    const int coff = half * 32;
    const int idx  = gidx[base_pn * KNB + k];
    const int gb   = bb * NPTS + idx;

    const float xix = points[base_pn * 3 + 0];
    const float xiy = points[base_pn * 3 + 1];
    const float xiz = points[base_pn * 3 + 2];
    const float gx  = points[gb * 3 + 0];
    const float gy  = points[gb * 3 + 1];
    const float gz  = points[gb * 3 + 2];
    const float dx = xix - gx, dy = xiy - gy, dz = xiz - gz;
    const float dist = sqrtf(dx*dx + dy*dy + dz*dz);

    ull gp[6];
    gp[0] = pack2(xix, xiy);
    gp[1] = pack2(xiz, gx);
    gp[2] = pack2(gy,  gz);
    gp[3] = pack2(dx,  dy);
    gp[4] = pack2(dz,  dist);
    gp[5] = pack2(1.0f, 0.0f);       // picks up (bias1, 0) from Wp[c][10..11]

    const float4* fp4 = reinterpret_cast<const float4*>(features + gb * CCH + coff);
    float* h1row = &s.h1[pt][k * H1S + coff];

    #pragma unroll
    for (int hh = 0; hh < 2; ++hh) {          // two halves: limits live f regs
      float4 f[4];
      #pragma unroll
      for (int j = 0; j < 4; ++j) f[j] = fp4[hh * 4 + j];
      #pragma unroll
      for (int j2 = 0; j2 < 4; ++j2) {
        const int jj = hh * 4 + j2;
        float4 res;
        float fv[4] = {f[j2].x, f[j2].y, f[j2].z, f[j2].w};
        float* rp = (float*)&res;
        #pragma unroll
        for (int q = 0; q < 4; ++q) {
          const int c = coff + jj * 4 + q;
          const ulonglong2* wrow = reinterpret_cast<const ulonglong2*>(&s.Wp[c][0]);
          ulonglong2 wa = wrow[0], wb = wrow[1], wc = wrow[2];
          ull e2 = 0ULL;
          fma2(e2, gp[0], wa.x);
          fma2(e2, gp[1], wa.y);
          fma2(e2, gp[2], wb.x);
          fma2(e2, gp[3], wb.y);
          fma2(e2, gp[4], wc.x);
          fma2(e2, gp[5], wc.y);             // + bias1
          float2 e = unpack2(e2);
          rp[q] = fmaxf(e.x + e.y, 0.0f) + fv[q];
        }
        *reinterpret_cast<float4*>(&h1row[jj * 4]) = res;
      }
    }
  }
  __syncthreads();

  // ---------------- Phase 2: h2 GEMM, f32x2 over d-pairs -------------------
  // thread (dt, kt): d-set {4dt..4dt+3} U {32+4dt..32+4dt+3}, k-rows kt*4..kt*4+3
  {
    const int dt = tp & 7;
    const int kt = tp >> 3;
    const float* h1p = &s.h1[pt][kt * 4 * H1S];

    ull acc[4][4];   // [k-row][pair j]: j0=(4dt,4dt+1) j1=(4dt+2,4dt+3) j2/j3 = +32
    #pragma unroll
    for (int kk = 0; kk < 4; ++kk)
      #pragma unroll
      for (int j = 0; j < 4; ++j) acc[kk][j] = 0ULL;

    #pragma unroll 2
    for (int c4 = 0; c4 < CCH; c4 += 4) {
      float ha[4][4];
      #pragma unroll
      for (int kk = 0; kk < 4; ++kk)
        *reinterpret_cast<float4*>(ha[kk]) =
            *reinterpret_cast<const float4*>(&h1p[kk * H1S + c4]);

      #pragma unroll
      for (int q = 0; q < 4; ++q) {
        const ulonglong2 wa =
            *reinterpret_cast<const ulonglong2*>(&s.Wg2[c4 + q][4 * dt]);       // banks dt*4: conflict-free
        const ulonglong2 wb =
            *reinterpret_cast<const ulonglong2*>(&s.Wg2[c4 + q][32 + 4 * dt]);
        #pragma unroll
        for (int kk = 0; kk < 4; ++kk) {
          const ull hp = pack2(ha[kk][q], ha[kk][q]);
          fma2(acc[kk][0], hp, wa.x);
          fma2(acc[kk][1], hp, wa.y);
          fma2(acc[kk][2], hp, wb.x);
          fma2(acc[kk][3], hp, wb.y);
        }
      }
    }

    const float wa0 = s.Watt[kt * 4 + 0];
    const float wa1 = s.Watt[kt * 4 + 1];
    const float wa2 = s.Watt[kt * 4 + 2];
    const float wa3 = s.Watt[kt * 4 + 3];

    float sp[8], mp[8];
    #pragma unroll
    for (int j = 0; j < 4; ++j) {
      const int dlo = (j < 2) ? (4 * dt + 2 * j) : (32 + 4 * dt + 2 * (j - 2));
      const float blo = s.bias2[dlo], bhi = s.bias2[dlo + 1];
      float2 t0 = unpack2(acc[0][j]);
      float2 t1 = unpack2(acc[1][j]);
      float2 t2 = unpack2(acc[2][j]);
      float2 t3 = unpack2(acc[3][j]);
      const float l0 = fmaxf(t0.x + blo, 0.0f), h0 = fmaxf(t0.y + bhi, 0.0f);
      const float l1 = fmaxf(t1.x + blo, 0.0f), h1v = fmaxf(t1.y + bhi, 0.0f);
      const float l2 = fmaxf(t2.x + blo, 0.0f), h2v = fmaxf(t2.y + bhi, 0.0f);
      const float l3 = fmaxf(t3.x + blo, 0.0f), h3v = fmaxf(t3.y + bhi, 0.0f);
      sp[2 * j + 0] = l0 * wa0 + l1 * wa1 + l2 * wa2 + l3 * wa3;
      sp[2 * j + 1] = h0 * wa0 + h1v * wa1 + h2v * wa2 + h3v * wa3;
      mp[2 * j + 0] = fmaxf(fmaxf(l0, l1), fmaxf(l2, l3));   // h2 >= 0
      mp[2 * j + 1] = fmaxf(fmaxf(h0, h1v), fmaxf(h2v, h3v));
    }

    // reduce over kt within warp (lane bits 3,4), cross-warp half via SMEM
    #pragma unroll
    for (int m = 8; m <= 16; m <<= 1) {
      #pragma unroll
      for (int j = 0; j < 8; ++j) {
        sp[j] += __shfl_xor_sync(0xffffffffu, sp[j], m);
        mp[j]  = fmaxf(mp[j], __shfl_xor_sync(0xffffffffu, mp[j], m));
      }
    }
    if ((tp & 24) == 0) {
      *reinterpret_cast<float4*>(&s.ps[pt][wip][4 * dt]) =
          make_float4(sp[0], sp[1], sp[2], sp[3]);
      *reinterpret_cast<float4*>(&s.ps[pt][wip][32 + 4 * dt]) =
          make_float4(sp[4], sp[5], sp[6], sp[7]);
      *reinterpret_cast<float4*>(&s.pm[pt][wip][4 * dt]) =
          make_float4(mp[0], mp[1], mp[2], mp[3]);
      *reinterpret_cast<float4*>(&s.pm[pt][wip][32 + 4 * dt]) =
          make_float4(mp[4], mp[5], mp[6], mp[7]);
    }
  }
  __syncthreads();

  // ---------------- Phase 3: softmax over C, pool, residual ----------------
  {
    const int c = tp;
    const float sv = s.ps[pt][0][c] + s.ps[pt][1][c];   // b_att softmax-invariant
    const float mv = fmaxf(s.pm[pt][0][c], s.pm[pt][1][c]);

    float mx = sv;
    #pragma unroll
    for (int m = 16; m >= 1; m >>= 1)
      mx = fmaxf(mx, __shfl_xor_sync(0xffffffffu, mx, m));
    if ((tp & 31) == 0) s.redA[pt][wip] = mx;
    __syncthreads();
    mx = fmaxf(s.redA[pt][0], s.redA[pt][1]);

    const float e = expf(sv - mx);
    float se = e;
    #pragma unroll
    for (int m = 16; m >= 1; m >>= 1)
      se += __shfl_xor_sync(0xffffffffu, se, m);
    if ((tp & 31) == 0) s.redB[pt][wip] = se;
    __syncthreads();
    se = s.redB[pt][0] + s.redB[pt][1];

    const float score = e / se;
    s.resv[pt][c] = score * mv + features[base_pn * CCH + c];
  }
  __syncthreads();

  // ---------------- Phase 4: out GEMM (f32x2) + LayerNorm + ReLU -----------
  {
    const int o = tp;
    const ulonglong2* wrow = reinterpret_cast<const ulonglong2*>(W_out + o * CCH);
    ull e2 = 0ULL;
    #pragma unroll
    for (int q = 0; q < 16; ++q) {
      ulonglong2 w = wrow[q];                                                   // L1-resident LDG.128
      ulonglong2 r = *reinterpret_cast<const ulonglong2*>(&s.resv[pt][q * 4]);  // broadcast LDS
      fma2(e2, r.x, w.x);
      fma2(e2, r.y, w.y);
    }
    float2 ee = unpack2(e2);
    float acc = ee.x + ee.y + b_out[o];

    float sum = acc, sq = acc * acc;
    #pragma unroll
    for (int m = 16; m >= 1; m >>= 1) {
      sum += __shfl_xor_sync(0xffffffffu, sum, m);
      sq  += __shfl_xor_sync(0xffffffffu, sq, m);
    }
    if ((tp & 31) == 0) { s.redC[pt][wip] = sum; s.redD[pt][wip] = sq; }
    __syncthreads();
    sum = s.redC[pt][0] + s.redC[pt][1];
    sq  = s.redD[pt][0] + s.redD[pt][1];

    const float mu  = sum * (1.0f / 64.0f);
    const float var = sq * (1.0f / 64.0f) - mu * mu;
    const float r   = rsqrtf(var + EPSF);
    const float y   = ln_g[o] * (acc - mu) * r + ln_b[o];
    out[base_pn * CCH + o] = fmaxf(y, 0.0f);
  }
}

extern "C" void kernel_launch(void* const* d_in, const int* in_sizes, int n_in,
                              void* d_out, int out_size) {
  const float* points   = (const float*)d_in[0];
  const float* features = (const float*)d_in[1];
  const int*   gidx     = (const int*)  d_in[2];
  const float* W_pos    = (const float*)d_in[3];
  const float* b_pos    = (const float*)d_in[4];
  const float* bn1_g    = (const float*)d_in[5];
  const float* bn1_b    = (const float*)d_in[6];
  const float* bn1_m    = (const float*)d_in[7];
  const float* bn1_v    = (const float*)d_in[8];
  const float* W_gcm    = (const float*)d_in[9];
  const float* b_gcm    = (const float*)d_in[10];
  const float* bn2_g    = (const float*)d_in[11];
  const float* bn2_b    = (const float*)d_in[12];
  const float* bn2_m    = (const float*)d_in[13];
  const float* bn2_v    = (const float*)d_in[14];
  const float* W_att    = (const float*)d_in[15];
  // d_in[16] = b_att (scalar): softmax-invariant, unused.
  const float* W_out    = (const float*)d_in[17];
  const float* b_out    = (const float*)d_in[18];
  const float* ln_g     = (const float*)d_in[19];
  const float* ln_b     = (const float*)d_in[20];
  float* out = (float*)d_out;

  const size_t smem = sizeof(Smem);
  cudaFuncSetAttribute((const void*)bridgenet_kernel,
                       cudaFuncAttributeMaxDynamicSharedMemorySize, (int)smem);

  const int total_pts = 2 * NPTS;             // 32768
  dim3 grid(total_pts / PPB);                 // 8192 blocks
  bridgenet_kernel<<<grid, NTHREADS, smem>>>(
      points, features, gidx, W_pos, b_pos,
      bn1_g, bn1_b, bn1_m, bn1_v,
      W_gcm, b_gcm, bn2_g, bn2_b, bn2_m, bn2_v,
      W_att, W_out, b_out, ln_g, ln_b, out);
}

// round 8
// speedup vs baseline: 1.1478x; 1.0415x over previous
#include <cuda_runtime.h>
#include <math.h>

typedef unsigned long long ull;

#define NPTS 16384
#define KNB 32
#define CCH 64
#define PPB 4          // points per block
#define NTHREADS 256
#define H1S 68         // h1 row stride (floats): float4-aligned
#define WGS 68         // Wg2 row stride
#define EPSF 1e-5f

// ---- packed fp32x2 helpers (FFMA2 only reachable via PTX) ----
__device__ __forceinline__ void fma2(ull& d, ull a, ull b) {
  asm("fma.rn.f32x2 %0, %1, %2, %0;" : "+l"(d) : "l"(a), "l"(b));
}
__device__ __forceinline__ ull pack2(float lo, float hi) {
  ull r; asm("mov.b64 %0, {%1, %2};" : "=l"(r) : "f"(lo), "f"(hi)); return r;
}
__device__ __forceinline__ float2 unpack2(ull v) {
  float2 r; asm("mov.b64 {%0, %1}, %2;" : "=f"(r.x), "=f"(r.y) : "l"(v)); return r;
}

struct Smem {
  float Wp[CCH][12];         // [c][0..9]=a1*W_pos, [10]=folded bias1, [11]=0
  float Wg2[CCH][WGS];       // [c][d] = a2[d]*W_gcm[d][c]
  float a1s[CCH], a2s[CCH], bias2[CCH];
  float Watt[KNB];
  int   nidx[PPB][KNB];      // neighbor indices
  float np3[PPB][KNB][3];    // neighbor xyz
  float h1[PPB][KNB * H1S];
  float ps[PPB][2][CCH];     // per-warp attention partials
  float pm[PPB][2][CCH];     // per-warp max partials
  float resv[PPB][CCH];
  float redA[PPB][2], redB[PPB][2], redC[PPB][2], redD[PPB][2];
};

__global__ __launch_bounds__(NTHREADS, 3)
void bridgenet_kernel(
    const float* __restrict__ points,
    const float* __restrict__ features,
    const int*   __restrict__ gidx,
    const float* __restrict__ W_pos,
    const float* __restrict__ b_pos,
    const float* __restrict__ bn1_g, const float* __restrict__ bn1_b,
    const float* __restrict__ bn1_m, const float* __restrict__ bn1_v,
    const float* __restrict__ W_gcm,
    const float* __restrict__ b_gcm,
    const float* __restrict__ bn2_g, const float* __restrict__ bn2_b,
    const float* __restrict__ bn2_m, const float* __restrict__ bn2_v,
    const float* __restrict__ W_att,
    const float* __restrict__ W_out,
    const float* __restrict__ b_out,
    const float* __restrict__ ln_g, const float* __restrict__ ln_b,
    float* __restrict__ out)
{
  extern __shared__ char smem_raw[];
  Smem& s = *reinterpret_cast<Smem*>(smem_raw);
  const int tid = threadIdx.x;

  const int pt = tid >> 6;           // point within block
  const int tp = tid & 63;           // thread within point
  const int wip = tp >> 5;           // warp within point
  const int p  = blockIdx.x * PPB + pt;
  const int bb = p >> 14;            // N = 16384
  const int nn = p & (NPTS - 1);
  const int base_pn = bb * NPTS + nn;

  // ---- Phase 0 (pre-sync): BN folding, neighbor idx + xyz staging --------
  if (tid < CCH) {
    float a1 = bn1_g[tid] * rsqrtf(bn1_v[tid] + EPSF);
    s.a1s[tid] = a1;
    s.Wp[tid][10] = a1 * (b_pos[tid] - bn1_m[tid]) + bn1_b[tid];
    s.Wp[tid][11] = 0.0f;
    float a2 = bn2_g[tid] * rsqrtf(bn2_v[tid] + EPSF);
    s.a2s[tid] = a2;
    s.bias2[tid] = a2 * (b_gcm[tid] - bn2_m[tid]) + bn2_b[tid];
  }
  if (tid >= CCH && tid < CCH + KNB) s.Watt[tid - CCH] = W_att[tid - CCH];

  if (tp < KNB) {                    // one thread per neighbor: idx + xyz once
    const int idx = gidx[base_pn * KNB + tp];
    s.nidx[pt][tp] = idx;
    const int gb = bb * NPTS + idx;
    s.np3[pt][tp][0] = points[gb * 3 + 0];
    s.np3[pt][tp][1] = points[gb * 3 + 1];
    s.np3[pt][tp][2] = points[gb * 3 + 2];
  }
  __syncthreads();

  // ---- Weight scatter + LINE-CONTIGUOUS feature gather into h1 -----------
  for (int i = tid; i < CCH * 10; i += NTHREADS) {
    int c = i / 10, g = i - c * 10;
    s.Wp[c][g] = s.a1s[c] * W_pos[i];
  }
  for (int i = tid; i < CCH * CCH; i += NTHREADS) {
    int d = i >> 6, c = i & 63;
    s.Wg2[c][d] = s.a2s[d] * W_gcm[i];     // W_gcm[d][c]
  }

  // gather: instruction j -> 16 lanes cover one full neighbor row (256B),
  // so each LDG.128 touches 4 complete 128B lines (vs 32 fragmented before).
  {
    const int chunk = tp & 15;               // 16B chunk within row
    const int rsub  = tp >> 4;               // 0..3
    #pragma unroll
    for (int j = 0; j < 8; ++j) {
      const int row = rsub + 4 * j;          // neighbor 0..31
      const int gb  = bb * NPTS + s.nidx[pt][row];
      const float4 v = *reinterpret_cast<const float4*>(features + gb * CCH + chunk * 4);
      *reinterpret_cast<float4*>(&s.h1[pt][row * H1S + chunk * 4]) = v;
    }
  }
  __syncthreads();

  // ---- Phase 1b: in-place add of relu(pos-encoding) ----------------------
  {
    const int k    = tp >> 1;
    const int half = tp & 1;
    const int coff = half * 32;

    const float xix = points[base_pn * 3 + 0];   // broadcast, L1-resident
    const float xiy = points[base_pn * 3 + 1];
    const float xiz = points[base_pn * 3 + 2];
    const float gx  = s.np3[pt][k][0];
    const float gy  = s.np3[pt][k][1];
    const float gz  = s.np3[pt][k][2];
    const float dx = xix - gx, dy = xiy - gy, dz = xiz - gz;
    const float dist = sqrtf(dx*dx + dy*dy + dz*dz);

    ull gp[6];
    gp[0] = pack2(xix, xiy);
    gp[1] = pack2(xiz, gx);
    gp[2] = pack2(gy,  gz);
    gp[3] = pack2(dx,  dy);
    gp[4] = pack2(dz,  dist);
    gp[5] = pack2(1.0f, 0.0f);       // picks up (bias1, 0) from Wp[c][10..11]

    float* h1row = &s.h1[pt][k * H1S + coff];
    #pragma unroll
    for (int jj = 0; jj < 8; ++jj) {
      float4 f4 = *reinterpret_cast<const float4*>(&h1row[jj * 4]);
      float fv[4] = {f4.x, f4.y, f4.z, f4.w};
      float4 res;
      float* rp = (float*)&res;
      #pragma unroll
      for (int q = 0; q < 4; ++q) {
        const int c = coff + jj * 4 + q;
        const ulonglong2* wrow = reinterpret_cast<const ulonglong2*>(&s.Wp[c][0]);
        ulonglong2 wa = wrow[0], wb = wrow[1], wc = wrow[2];
        ull e2 = 0ULL;
        fma2(e2, gp[0], wa.x);
        fma2(e2, gp[1], wa.y);
        fma2(e2, gp[2], wb.x);
        fma2(e2, gp[3], wb.y);
        fma2(e2, gp[4], wc.x);
        fma2(e2, gp[5], wc.y);             // + bias1
        float2 e = unpack2(e2);
        rp[q] = fmaxf(e.x + e.y, 0.0f) + fv[q];
      }
      *reinterpret_cast<float4*>(&h1row[jj * 4]) = res;
    }
  }
  __syncthreads();

  // ---------------- Phase 2: h2 GEMM, f32x2 over d-pairs -------------------
  {
    const int dt = tp & 7;
    const int kt = tp >> 3;
    const float* h1p = &s.h1[pt][kt * 4 * H1S];

    ull acc[4][4];   // [k-row][pair j]
    #pragma unroll
    for (int kk = 0; kk < 4; ++kk)
      #pragma unroll
      for (int j = 0; j < 4; ++j) acc[kk][j] = 0ULL;

    #pragma unroll 2
    for (int c4 = 0; c4 < CCH; c4 += 4) {
      float ha[4][4];
      #pragma unroll
      for (int kk = 0; kk < 4; ++kk)
        *reinterpret_cast<float4*>(ha[kk]) =
            *reinterpret_cast<const float4*>(&h1p[kk * H1S + c4]);

      #pragma unroll
      for (int q = 0; q < 4; ++q) {
        const ulonglong2 wa =
            *reinterpret_cast<const ulonglong2*>(&s.Wg2[c4 + q][4 * dt]);
        const ulonglong2 wb =
            *reinterpret_cast<const ulonglong2*>(&s.Wg2[c4 + q][32 + 4 * dt]);
        #pragma unroll
        for (int kk = 0; kk < 4; ++kk) {
          const ull hp = pack2(ha[kk][q], ha[kk][q]);
          fma2(acc[kk][0], hp, wa.x);
          fma2(acc[kk][1], hp, wa.y);
          fma2(acc[kk][2], hp, wb.x);
          fma2(acc[kk][3], hp, wb.y);
        }
      }
    }

    const float wa0 = s.Watt[kt * 4 + 0];
    const float wa1 = s.Watt[kt * 4 + 1];
    const float wa2 = s.Watt[kt * 4 + 2];
    const float wa3 = s.Watt[kt * 4 + 3];

    float sp[8], mp[8];
    #pragma unroll
    for (int j = 0; j < 4; ++j) {
      const int dlo = (j < 2) ? (4 * dt + 2 * j) : (32 + 4 * dt + 2 * (j - 2));
      const float blo = s.bias2[dlo], bhi = s.bias2[dlo + 1];
      float2 t0 = unpack2(acc[0][j]);
      float2 t1 = unpack2(acc[1][j]);
      float2 t2 = unpack2(acc[2][j]);
      float2 t3 = unpack2(acc[3][j]);
      const float l0 = fmaxf(t0.x + blo, 0.0f), h0 = fmaxf(t0.y + bhi, 0.0f);
      const float l1 = fmaxf(t1.x + blo, 0.0f), h1v = fmaxf(t1.y + bhi, 0.0f);
      const float l2 = fmaxf(t2.x + blo, 0.0f), h2v = fmaxf(t2.y + bhi, 0.0f);
      const float l3 = fmaxf(t3.x + blo, 0.0f), h3v = fmaxf(t3.y + bhi, 0.0f);
      sp[2 * j + 0] = l0 * wa0 + l1 * wa1 + l2 * wa2 + l3 * wa3;
      sp[2 * j + 1] = h0 * wa0 + h1v * wa1 + h2v * wa2 + h3v * wa3;
      mp[2 * j + 0] = fmaxf(fmaxf(l0, l1), fmaxf(l2, l3));   // h2 >= 0
      mp[2 * j + 1] = fmaxf(fmaxf(h0, h1v), fmaxf(h2v, h3v));
    }

    #pragma unroll
    for (int m = 8; m <= 16; m <<= 1) {
      #pragma unroll
      for (int j = 0; j < 8; ++j) {
        sp[j] += __shfl_xor_sync(0xffffffffu, sp[j], m);
        mp[j]  = fmaxf(mp[j], __shfl_xor_sync(0xffffffffu, mp[j], m));
      }
    }
    if ((tp & 24) == 0) {
      *reinterpret_cast<float4*>(&s.ps[pt][wip][4 * dt]) =
          make_float4(sp[0], sp[1], sp[2], sp[3]);
      *reinterpret_cast<float4*>(&s.ps[pt][wip][32 + 4 * dt]) =
          make_float4(sp[4], sp[5], sp[6], sp[7]);
      *reinterpret_cast<float4*>(&s.pm[pt][wip][4 * dt]) =
          make_float4(mp[0], mp[1], mp[2], mp[3]);
      *reinterpret_cast<float4*>(&s.pm[pt][wip][32 + 4 * dt]) =
          make_float4(mp[4], mp[5], mp[6], mp[7]);
    }
  }
  __syncthreads();

  // ---------------- Phase 3: softmax over C, pool, residual ----------------
  {
    const int c = tp;
    const float sv = s.ps[pt][0][c] + s.ps[pt][1][c];   // b_att softmax-invariant
    const float mv = fmaxf(s.pm[pt][0][c], s.pm[pt][1][c]);

    float mx = sv;
    #pragma unroll
    for (int m = 16; m >= 1; m >>= 1)
      mx = fmaxf(mx, __shfl_xor_sync(0xffffffffu, mx, m));
    if ((tp & 31) == 0) s.redA[pt][wip] = mx;
    __syncthreads();
    mx = fmaxf(s.redA[pt][0], s.redA[pt][1]);

    const float e = expf(sv - mx);
    float se = e;
    #pragma unroll
    for (int m = 16; m >= 1; m >>= 1)
      se += __shfl_xor_sync(0xffffffffu, se, m);
    if ((tp & 31) == 0) s.redB[pt][wip] = se;
    __syncthreads();
    se = s.redB[pt][0] + s.redB[pt][1];

    const float score = e / se;
    s.resv[pt][c] = score * mv + features[base_pn * CCH + c];
  }
  __syncthreads();

  // ---------------- Phase 4: out GEMM (f32x2) + LayerNorm + ReLU -----------
  {
    const int o = tp;
    const ulonglong2* wrow = reinterpret_cast<const ulonglong2*>(W_out + o * CCH);
    ull e2 = 0ULL;
    #pragma unroll
    for (int q = 0; q < 16; ++q) {
      ulonglong2 w = wrow[q];                                                   // L1-resident LDG.128
      ulonglong2 r = *reinterpret_cast<const ulonglong2*>(&s.resv[pt][q * 4]);  // broadcast LDS
      fma2(e2, r.x, w.x);
      fma2(e2, r.y, w.y);
    }
    float2 ee = unpack2(e2);
    float acc = ee.x + ee.y + b_out[o];

    float sum = acc, sq = acc * acc;
    #pragma unroll
    for (int m = 16; m >= 1; m >>= 1) {
      sum += __shfl_xor_sync(0xffffffffu, sum, m);
      sq  += __shfl_xor_sync(0xffffffffu, sq, m);
    }
    if ((tp & 31) == 0) { s.redC[pt][wip] = sum; s.redD[pt][wip] = sq; }
    __syncthreads();
    sum = s.redC[pt][0] + s.redC[pt][1];
    sq  = s.redD[pt][0] + s.redD[pt][1];

    const float mu  = sum * (1.0f / 64.0f);
    const float var = sq * (1.0f / 64.0f) - mu * mu;
    const float r   = rsqrtf(var + EPSF);
    const float y   = ln_g[o] * (acc - mu) * r + ln_b[o];
    out[base_pn * CCH + o] = fmaxf(y, 0.0f);
  }
}

extern "C" void kernel_launch(void* const* d_in, const int* in_sizes, int n_in,
                              void* d_out, int out_size) {
  const float* points   = (const float*)d_in[0];
  const float* features = (const float*)d_in[1];
  const int*   gidx     = (const int*)  d_in[2];
  const float* W_pos    = (const float*)d_in[3];
  const float* b_pos    = (const float*)d_in[4];
  const float* bn1_g    = (const float*)d_in[5];
  const float* bn1_b    = (const float*)d_in[6];
  const float* bn1_m    = (const float*)d_in[7];
  const float* bn1_v    = (const float*)d_in[8];
  const float* W_gcm    = (const float*)d_in[9];
  const float* b_gcm    = (const float*)d_in[10];
  const float* bn2_g    = (const float*)d_in[11];
  const float* bn2_b    = (const float*)d_in[12];
  const float* bn2_m    = (const float*)d_in[13];
  const float* bn2_v    = (const float*)d_in[14];
  const float* W_att    = (const float*)d_in[15];
  // d_in[16] = b_att (scalar): softmax-invariant, unused.
  const float* W_out    = (const float*)d_in[17];
  const float* b_out    = (const float*)d_in[18];
  const float* ln_g     = (const float*)d_in[19];
  const float* ln_b     = (const float*)d_in[20];
  float* out = (float*)d_out;

  const size_t smem = sizeof(Smem);
  cudaFuncSetAttribute((const void*)bridgenet_kernel,
                       cudaFuncAttributeMaxDynamicSharedMemorySize, (int)smem);

  const int total_pts = 2 * NPTS;             // 32768
  dim3 grid(total_pts / PPB);                 // 8192 blocks
  bridgenet_kernel<<<grid, NTHREADS, smem>>>(
      points, features, gidx, W_pos, b_pos,
      bn1_g, bn1_b, bn1_m, bn1_v,
      W_gcm, b_gcm, bn2_g, bn2_b, bn2_m, bn2_v,
      W_att, W_out, b_out, ln_g, ln_b, out);
}

// round 11
// speedup vs baseline: 1.2762x; 1.1118x over previous
#include <cuda_runtime.h>
#include <math.h>

typedef unsigned long long ull;
typedef unsigned int uint32;

#define NPTS 16384
#define KNB 32
#define CCH 64
#define PPB 4          // points per block
#define NTHREADS 256
#define H1S 68         // h1 row stride (floats): float4-aligned; 4m+q bank pattern
#define WGS 72         // Wg2 row stride: 72 mod 32 = 8 -> conflict-free B fragments
#define EPSF 1e-5f

// ---- packed fp32x2 helpers (used in phases 1 & 4) ----
__device__ __forceinline__ void fma2(ull& d, ull a, ull b) {
  asm("fma.rn.f32x2 %0, %1, %2, %0;" : "+l"(d) : "l"(a), "l"(b));
}
__device__ __forceinline__ ull pack2(float lo, float hi) {
  ull r; asm("mov.b64 %0, {%1, %2};" : "=l"(r) : "f"(lo), "f"(hi)); return r;
}
__device__ __forceinline__ float2 unpack2(ull v) {
  float2 r; asm("mov.b64 {%0, %1}, %2;" : "=f"(r.x), "=f"(r.y) : "l"(v)); return r;
}

// ---- tf32 MMA: D += A(16x8) * B(8x8), fp32 accumulate ----
__device__ __forceinline__ void mma_tf32(float* d,
    uint32 a0, uint32 a1, uint32 a2, uint32 a3, uint32 b0, uint32 b1) {
  asm("mma.sync.aligned.m16n8k8.row.col.f32.tf32.tf32.f32 "
      "{%0,%1,%2,%3}, {%4,%5,%6,%7}, {%8,%9}, {%0,%1,%2,%3};"
      : "+f"(d[0]), "+f"(d[1]), "+f"(d[2]), "+f"(d[3])
      : "r"(a0), "r"(a1), "r"(a2), "r"(a3), "r"(b0), "r"(b1));
}
// split f32 into tf32-exact hi + residual lo (lo truncated by HW at 2^-21 rel)
__device__ __forceinline__ void split_tf32(float x, uint32& hi, uint32& lo) {
  hi = __float_as_uint(x) & 0xFFFFE000u;
  lo = __float_as_uint(x - __uint_as_float(hi));
}

struct Smem {
  float Wp[CCH][12];         // [c][0..9]=a1*W_pos, [10]=folded bias1, [11]=0
  float Wg2[CCH][WGS];       // [c][d] = a2[d]*W_gcm[d][c]
  float a1s[CCH], a2s[CCH], bias2[CCH];
  float Watt[KNB];
  int   nidx[PPB][KNB];      // neighbor indices
  float np3[PPB][KNB][3];    // neighbor xyz
  float h1[PPB][KNB * H1S];
  float ps[PPB][2][CCH];     // per-warp attention partials
  float pm[PPB][2][CCH];     // per-warp max partials
  float resv[PPB][CCH];
  float redA[PPB][2], redB[PPB][2], redC[PPB][2], redD[PPB][2];
};

__global__ __launch_bounds__(NTHREADS, 3)
void bridgenet_kernel(
    const float* __restrict__ points,
    const float* __restrict__ features,
    const int*   __restrict__ gidx,
    const float* __restrict__ W_pos,
    const float* __restrict__ b_pos,
    const float* __restrict__ bn1_g, const float* __restrict__ bn1_b,
    const float* __restrict__ bn1_m, const float* __restrict__ bn1_v,
    const float* __restrict__ W_gcm,
    const float* __restrict__ b_gcm,
    const float* __restrict__ bn2_g, const float* __restrict__ bn2_b,
    const float* __restrict__ bn2_m, const float* __restrict__ bn2_v,
    const float* __restrict__ W_att,
    const float* __restrict__ W_out,
    const float* __restrict__ b_out,
    const float* __restrict__ ln_g, const float* __restrict__ ln_b,
    float* __restrict__ out)
{
  extern __shared__ char smem_raw[];
  Smem& s = *reinterpret_cast<Smem*>(smem_raw);
  const int tid = threadIdx.x;

  const int pt = tid >> 6;           // point within block
  const int tp = tid & 63;           // thread within point
  const int wip = tp >> 5;           // warp within point
  const int p  = blockIdx.x * PPB + pt;
  const int bb = p >> 14;            // N = 16384
  const int nn = p & (NPTS - 1);
  const int base_pn = bb * NPTS + nn;

  // ---- Phase 0 (pre-sync): BN folding, neighbor idx + xyz staging --------
  if (tid < CCH) {
    float a1 = bn1_g[tid] * rsqrtf(bn1_v[tid] + EPSF);
    s.a1s[tid] = a1;
    s.Wp[tid][10] = a1 * (b_pos[tid] - bn1_m[tid]) + bn1_b[tid];
    s.Wp[tid][11] = 0.0f;
    float a2 = bn2_g[tid] * rsqrtf(bn2_v[tid] + EPSF);
    s.a2s[tid] = a2;
    s.bias2[tid] = a2 * (b_gcm[tid] - bn2_m[tid]) + bn2_b[tid];
  }
  if (tid >= CCH && tid < CCH + KNB) s.Watt[tid - CCH] = W_att[tid - CCH];

  if (tp < KNB) {                    // one thread per neighbor: idx + xyz once
    const int idx = gidx[base_pn * KNB + tp];
    s.nidx[pt][tp] = idx;
    const int gb = bb * NPTS + idx;
    s.np3[pt][tp][0] = points[gb * 3 + 0];
    s.np3[pt][tp][1] = points[gb * 3 + 1];
    s.np3[pt][tp][2] = points[gb * 3 + 2];
  }
  __syncthreads();

  // ---- Weight scatter + LINE-CONTIGUOUS feature gather into h1 -----------
  for (int i = tid; i < CCH * 10; i += NTHREADS) {
    int c = i / 10, g = i - c * 10;
    s.Wp[c][g] = s.a1s[c] * W_pos[i];
  }
  for (int i = tid; i < CCH * CCH; i += NTHREADS) {
    int d = i >> 6, c = i & 63;
    s.Wg2[c][d] = s.a2s[d] * W_gcm[i];     // W_gcm[d][c]
  }

  {
    const int chunk = tp & 15;               // 16B chunk within row
    const int rsub  = tp >> 4;               // 0..3
    #pragma unroll
    for (int j = 0; j < 8; ++j) {
      const int row = rsub + 4 * j;          // neighbor 0..31
      const int gb  = bb * NPTS + s.nidx[pt][row];
      const float4 v = *reinterpret_cast<const float4*>(features + gb * CCH + chunk * 4);
      *reinterpret_cast<float4*>(&s.h1[pt][row * H1S + chunk * 4]) = v;
    }
  }
  __syncthreads();

  // ---- Phase 1b: in-place add of relu(pos-encoding) ----------------------
  {
    const int k    = tp >> 1;
    const int half = tp & 1;
    const int coff = half * 32;

    const float xix = points[base_pn * 3 + 0];   // broadcast, L1-resident
    const float xiy = points[base_pn * 3 + 1];
    const float xiz = points[base_pn * 3 + 2];
    const float gx  = s.np3[pt][k][0];
    const float gy  = s.np3[pt][k][1];
    const float gz  = s.np3[pt][k][2];
    const float dx = xix - gx, dy = xiy - gy, dz = xiz - gz;
    const float dist = sqrtf(dx*dx + dy*dy + dz*dz);

    ull gp[6];
    gp[0] = pack2(xix, xiy);
    gp[1] = pack2(xiz, gx);
    gp[2] = pack2(gy,  gz);
    gp[3] = pack2(dx,  dy);
    gp[4] = pack2(dz,  dist);
    gp[5] = pack2(1.0f, 0.0f);       // picks up (bias1, 0) from Wp[c][10..11]

    float* h1row = &s.h1[pt][k * H1S + coff];
    #pragma unroll
    for (int jj = 0; jj < 8; ++jj) {
      float4 f4 = *reinterpret_cast<const float4*>(&h1row[jj * 4]);
      float fv[4] = {f4.x, f4.y, f4.z, f4.w};
      float4 res;
      float* rp = (float*)&res;
      #pragma unroll
      for (int q = 0; q < 4; ++q) {
        const int c = coff + jj * 4 + q;
        const ulonglong2* wrow = reinterpret_cast<const ulonglong2*>(&s.Wp[c][0]);
        ulonglong2 wa = wrow[0], wb = wrow[1], wc = wrow[2];
        ull e2 = 0ULL;
        fma2(e2, gp[0], wa.x);
        fma2(e2, gp[1], wa.y);
        fma2(e2, gp[2], wb.x);
        fma2(e2, gp[3], wb.y);
        fma2(e2, gp[4], wc.x);
        fma2(e2, gp[5], wc.y);             // + bias1
        float2 e = unpack2(e2);
        rp[q] = fmaxf(e.x + e.y, 0.0f) + fv[q];
      }
      *reinterpret_cast<float4*>(&h1row[jj * 4]) = res;
    }
  }
  __syncthreads();

  // ---------------- Phase 2: h2 GEMM via tf32 MMA (3-pass hi/lo) -----------
  // Warp wip handles neighbor rows m = 16*wip .. 16*wip+15, all 64 channels.
  // A = h1[m][c] (row-major), B = Wg2[c][d] (col-major k x n fragment).
  {
    const int lane = tp & 31;
    const int g4 = lane >> 2;        // 0..7
    const int q4 = lane & 3;         // 0..3
    const int mbase = wip * 16;

    float acc[8][4];
    #pragma unroll
    for (int t = 0; t < 8; ++t)
      #pragma unroll
      for (int j = 0; j < 4; ++j) acc[t][j] = 0.0f;

    const float* h1b = &s.h1[pt][0];

    #pragma unroll
    for (int ks = 0; ks < 8; ++ks) {
      // A fragment: rows mbase+g4 / +8 ; cols 8ks+q4 / +4  (lane-distinct LDS.32)
      const int r0 = (mbase + g4) * H1S + ks * 8 + q4;
      const int r1 = r0 + 8 * H1S;
      const float a0 = h1b[r0],     a1 = h1b[r1];
      const float a2f = h1b[r0 + 4], a3 = h1b[r1 + 4];
      uint32 ah0, al0, ah1, al1, ah2, al2, ah3, al3;
      split_tf32(a0,  ah0, al0);
      split_tf32(a1,  ah1, al1);
      split_tf32(a2f, ah2, al2);
      split_tf32(a3,  ah3, al3);

      #pragma unroll
      for (int t = 0; t < 8; ++t) {
        // B fragment: rows (channels) 8ks+q4 / +4, col (d) 8t+g4
        const float b0 = s.Wg2[ks * 8 + q4][t * 8 + g4];
        const float b1 = s.Wg2[ks * 8 + q4 + 4][t * 8 + g4];
        uint32 bh0, bl0, bh1, bl1;
        split_tf32(b0, bh0, bl0);
        split_tf32(b1, bh1, bl1);
        mma_tf32(acc[t], ah0, ah1, ah2, ah3, bh0, bh1);   // hi*hi
        mma_tf32(acc[t], ah0, ah1, ah2, ah3, bl0, bl1);   // hi*lo
        mma_tf32(acc[t], al0, al1, al2, al3, bh0, bh1);   // lo*hi
      }
    }

    // Epilogue: bias + ReLU, attention dot over k, max over k.
    // Lane holds rows m0 = mbase+g4 and m0+8; cols n0 = 8t+2q4, n0+1.
    const float wv0 = s.Watt[mbase + g4];
    const float wv1 = s.Watt[mbase + g4 + 8];
    #pragma unroll
    for (int t = 0; t < 8; ++t) {
      const int n0 = t * 8 + 2 * q4;
      const float b0 = s.bias2[n0], b1 = s.bias2[n0 + 1];
      const float h00 = fmaxf(acc[t][0] + b0, 0.0f);
      const float h01 = fmaxf(acc[t][1] + b1, 0.0f);
      const float h10 = fmaxf(acc[t][2] + b0, 0.0f);
      const float h11 = fmaxf(acc[t][3] + b1, 0.0f);
      float spa = h00 * wv0 + h10 * wv1;
      float spb = h01 * wv0 + h11 * wv1;
      float mpa = fmaxf(h00, h10);           // h2 >= 0
      float mpb = fmaxf(h01, h11);
      #pragma unroll
      for (int m = 4; m <= 16; m <<= 1) {    // reduce across g4 lanes
        spa += __shfl_xor_sync(0xffffffffu, spa, m);
        spb += __shfl_xor_sync(0xffffffffu, spb, m);
        mpa = fmaxf(mpa, __shfl_xor_sync(0xffffffffu, mpa, m));
        mpb = fmaxf(mpb, __shfl_xor_sync(0xffffffffu, mpb, m));
      }
      if (g4 == 0) {
        *reinterpret_cast<float2*>(&s.ps[pt][wip][n0]) = make_float2(spa, spb);
        *reinterpret_cast<float2*>(&s.pm[pt][wip][n0]) = make_float2(mpa, mpb);
      }
    }
  }
  __syncthreads();

  // ---------------- Phase 3: softmax over C, pool, residual ----------------
  {
    const int c = tp;
    const float sv = s.ps[pt][0][c] + s.ps[pt][1][c];   // b_att softmax-invariant
    const float mv = fmaxf(s.pm[pt][0][c], s.pm[pt][1][c]);

    float mx = sv;
    #pragma unroll
    for (int m = 16; m >= 1; m >>= 1)
      mx = fmaxf(mx, __shfl_xor_sync(0xffffffffu, mx, m));
    if ((tp & 31) == 0) s.redA[pt][wip] = mx;
    __syncthreads();
    mx = fmaxf(s.redA[pt][0], s.redA[pt][1]);

    const float e = expf(sv - mx);
    float se = e;
    #pragma unroll
    for (int m = 16; m >= 1; m >>= 1)
      se += __shfl_xor_sync(0xffffffffu, se, m);
    if ((tp & 31) == 0) s.redB[pt][wip] = se;
    __syncthreads();
    se = s.redB[pt][0] + s.redB[pt][1];

    const float score = e / se;
    s.resv[pt][c] = score * mv + features[base_pn * CCH + c];
  }
  __syncthreads();

  // ---------------- Phase 4: out GEMM (f32x2) + LayerNorm + ReLU -----------
  {
    const int o = tp;
    const ulonglong2* wrow = reinterpret_cast<const ulonglong2*>(W_out + o * CCH);
    ull e2 = 0ULL;
    #pragma unroll
    for (int q = 0; q < 16; ++q) {
      ulonglong2 w = wrow[q];                                                   // L1-resident LDG.128
      ulonglong2 r = *reinterpret_cast<const ulonglong2*>(&s.resv[pt][q * 4]);  // broadcast LDS
      fma2(e2, r.x, w.x);
      fma2(e2, r.y, w.y);
    }
    float2 ee = unpack2(e2);
    float acc = ee.x + ee.y + b_out[o];

    float sum = acc, sq = acc * acc;
    #pragma unroll
    for (int m = 16; m >= 1; m >>= 1) {
      sum += __shfl_xor_sync(0xffffffffu, sum, m);
      sq  += __shfl_xor_sync(0xffffffffu, sq, m);
    }
    if ((tp & 31) == 0) { s.redC[pt][wip] = sum; s.redD[pt][wip] = sq; }
    __syncthreads();
    sum = s.redC[pt][0] + s.redC[pt][1];
    sq  = s.redD[pt][0] + s.redD[pt][1];

    const float mu  = sum * (1.0f / 64.0f);
    const float var = sq * (1.0f / 64.0f) - mu * mu;
    const float r   = rsqrtf(var + EPSF);
    const float y   = ln_g[o] * (acc - mu) * r + ln_b[o];
    out[base_pn * CCH + o] = fmaxf(y, 0.0f);
  }
}

extern "C" void kernel_launch(void* const* d_in, const int* in_sizes, int n_in,
                              void* d_out, int out_size) {
  const float* points   = (const float*)d_in[0];
  const float* features = (const float*)d_in[1];
  const int*   gidx     = (const int*)  d_in[2];
  const float* W_pos    = (const float*)d_in[3];
  const float* b_pos    = (const float*)d_in[4];
  const float* bn1_g    = (const float*)d_in[5];
  const float* bn1_b    = (const float*)d_in[6];
  const float* bn1_m    = (const float*)d_in[7];
  const float* bn1_v    = (const float*)d_in[8];
  const float* W_gcm    = (const float*)d_in[9];
  const float* b_gcm    = (const float*)d_in[10];
  const float* bn2_g    = (const float*)d_in[11];
  const float* bn2_b    = (const float*)d_in[12];
  const float* bn2_m    = (const float*)d_in[13];
  const float* bn2_v    = (const float*)d_in[14];
  const float* W_att    = (const float*)d_in[15];
  // d_in[16] = b_att (scalar): softmax-invariant, unused.
  const float* W_out    = (const float*)d_in[17];
  const float* b_out    = (const float*)d_in[18];
  const float* ln_g     = (const float*)d_in[19];
  const float* ln_b     = (const float*)d_in[20];
  float* out = (float*)d_out;

  const size_t smem = sizeof(Smem);
  cudaFuncSetAttribute((const void*)bridgenet_kernel,
                       cudaFuncAttributeMaxDynamicSharedMemorySize, (int)smem);

  const int total_pts = 2 * NPTS;             // 32768
  dim3 grid(total_pts / PPB);                 // 8192 blocks
  bridgenet_kernel<<<grid, NTHREADS, smem>>>(
      points, features, gidx, W_pos, b_pos,
      bn1_g, bn1_b, bn1_m, bn1_v,
      W_gcm, b_gcm, bn2_g, bn2_b, bn2_m, bn2_v,
      W_att, W_out, b_out, ln_g, ln_b, out);
}

// round 12
// speedup vs baseline: 1.7330x; 1.3579x over previous
#include <cuda_runtime.h>
#include <math.h>

typedef unsigned long long ull;
typedef unsigned int uint32;

#define NPTS 16384
#define KNB 32
#define CCH 64
#define PPB 4          // points per block
#define NTHREADS 256
#define H1S 68         // h1 row stride: aligned, conflict-free fragments
#define WGS 72         // Wg2 row stride: conflict-free B fragments
#define WPS 72         // WpT row stride
#define GS  20         // geo row stride: conflict-free A fragments
#define WOS 68         // wout row stride (aliased into Wg2 space)
#define EPSF 1e-5f

// ---- packed fp32x2 helpers (phase 4) ----
__device__ __forceinline__ void fma2(ull& d, ull a, ull b) {
  asm("fma.rn.f32x2 %0, %1, %2, %0;" : "+l"(d) : "l"(a), "l"(b));
}
__device__ __forceinline__ float2 unpack2(ull v) {
  float2 r; asm("mov.b64 {%0, %1}, %2;" : "=f"(r.x), "=f"(r.y) : "l"(v)); return r;
}

// ---- tf32 MMA: D += A(16x8) * B(8x8), fp32 accumulate ----
__device__ __forceinline__ void mma_tf32(float* d,
    uint32 a0, uint32 a1, uint32 a2, uint32 a3, uint32 b0, uint32 b1) {
  asm("mma.sync.aligned.m16n8k8.row.col.f32.tf32.tf32.f32 "
      "{%0,%1,%2,%3}, {%4,%5,%6,%7}, {%8,%9}, {%0,%1,%2,%3};"
      : "+f"(d[0]), "+f"(d[1]), "+f"(d[2]), "+f"(d[3])
      : "r"(a0), "r"(a1), "r"(a2), "r"(a3), "r"(b0), "r"(b1));
}
__device__ __forceinline__ void split_tf32(float x, uint32& hi, uint32& lo) {
  hi = __float_as_uint(x) & 0xFFFFE000u;
  lo = __float_as_uint(x - __uint_as_float(hi));
}

struct Smem {
  float WpT[16][WPS];            // [g][c]: rows 0-9 = a1*W_pos^T, row 10 = bias1, 11-15 = 0
  union {                        // Wg2 (phases 1-2) then wout (phases 3-4)
    float Wg2[CCH][WGS];         // [c][d] = a2[d]*W_gcm[d][c]
    float wout_raw[CCH * WGS];   // wout[o*WOS + c] = W_out[o][c]
  } w;
  float a1s[CCH], a2s[CCH], bias1a[CCH], bias2[CCH];
  float Watt[KNB];
  int   nidx[PPB][KNB];
  float h1[PPB][KNB * H1S];
  union {                        // geo (phase 1) then reduction scratch (phases 2-4)
    float geo[PPB][KNB][GS];
    struct {
      float ps[PPB][2][CCH];
      float pm[PPB][2][CCH];
      float resv[PPB][CCH];
      float redA[PPB][2], redB[PPB][2], redC[PPB][2], redD[PPB][2];
    } t;
  } u;
};

__global__ __launch_bounds__(NTHREADS, 3)
void bridgenet_kernel(
    const float* __restrict__ points,
    const float* __restrict__ features,
    const int*   __restrict__ gidx,
    const float* __restrict__ W_pos,
    const float* __restrict__ b_pos,
    const float* __restrict__ bn1_g, const float* __restrict__ bn1_b,
    const float* __restrict__ bn1_m, const float* __restrict__ bn1_v,
    const float* __restrict__ W_gcm,
    const float* __restrict__ b_gcm,
    const float* __restrict__ bn2_g, const float* __restrict__ bn2_b,
    const float* __restrict__ bn2_m, const float* __restrict__ bn2_v,
    const float* __restrict__ W_att,
    const float* __restrict__ W_out,
    const float* __restrict__ b_out,
    const float* __restrict__ ln_g, const float* __restrict__ ln_b,
    float* __restrict__ out)
{
  extern __shared__ char smem_raw[];
  Smem& s = *reinterpret_cast<Smem*>(smem_raw);
  const int tid = threadIdx.x;

  const int pt = tid >> 6;           // point within block
  const int tp = tid & 63;           // thread within point
  const int wip = tp >> 5;           // warp within point
  const int p  = blockIdx.x * PPB + pt;
  const int bb = p >> 14;            // N = 16384
  const int nn = p & (NPTS - 1);
  const int base_pn = bb * NPTS + nn;

  // ---- Phase 0: BN folding + neighbor idx + geo staging -------------------
  if (tid < CCH) {
    float a1 = bn1_g[tid] * rsqrtf(bn1_v[tid] + EPSF);
    s.a1s[tid] = a1;
    s.bias1a[tid] = a1 * (b_pos[tid] - bn1_m[tid]) + bn1_b[tid];
    float a2 = bn2_g[tid] * rsqrtf(bn2_v[tid] + EPSF);
    s.a2s[tid] = a2;
    s.bias2[tid] = a2 * (b_gcm[tid] - bn2_m[tid]) + bn2_b[tid];
  }
  if (tid >= CCH && tid < CCH + KNB) s.Watt[tid - CCH] = W_att[tid - CCH];

  if (tp < KNB) {                    // one thread per (pt, neighbor)
    const int idx = gidx[base_pn * KNB + tp];
    s.nidx[pt][tp] = idx;
    const int gb = bb * NPTS + idx;
    const float xix = points[base_pn * 3 + 0];
    const float xiy = points[base_pn * 3 + 1];
    const float xiz = points[base_pn * 3 + 2];
    const float gx = points[gb * 3 + 0];
    const float gy = points[gb * 3 + 1];
    const float gz = points[gb * 3 + 2];
    const float dx = xix - gx, dy = xiy - gy, dz = xiz - gz;
    const float dist = sqrtf(dx*dx + dy*dy + dz*dz);
    float* gr = &s.u.geo[pt][tp][0];
    gr[0] = xix; gr[1] = xiy; gr[2] = xiz;
    gr[3] = gx;  gr[4] = gy;  gr[5] = gz;
    gr[6] = dx;  gr[7] = dy;  gr[8] = dz;
    gr[9] = dist; gr[10] = 1.0f;               // 1.0 pairs with bias row of WpT
    gr[11] = 0.0f; gr[12] = 0.0f; gr[13] = 0.0f; gr[14] = 0.0f; gr[15] = 0.0f;
  }
  __syncthreads();

  // ---- Weight scatter + line-contiguous feature gather into h1 ------------
  for (int i = tid; i < 16 * CCH; i += NTHREADS) {
    const int g = i >> 6, c = i & 63;
    float v = 0.0f;
    if (g < 10)       v = s.a1s[c] * W_pos[c * 10 + g];
    else if (g == 10) v = s.bias1a[c];
    s.WpT[g][c] = v;
  }
  for (int i = tid; i < CCH * CCH; i += NTHREADS) {
    const int d = i >> 6, c = i & 63;
    s.w.Wg2[c][d] = s.a2s[d] * W_gcm[i];      // W_gcm[d][c]
  }
  {
    const int chunk = tp & 15;                // 16B chunk within feature row
    const int rsub  = tp >> 4;                // 0..3
    #pragma unroll
    for (int j = 0; j < 8; ++j) {
      const int row = rsub + 4 * j;           // neighbor 0..31
      const int gb  = bb * NPTS + s.nidx[pt][row];
      const float4 v = *reinterpret_cast<const float4*>(features + gb * CCH + chunk * 4);
      *reinterpret_cast<float4*>(&s.h1[pt][row * H1S + chunk * 4]) = v;
    }
  }
  __syncthreads();

  const int lane = tp & 31;
  const int g4 = lane >> 2;          // 0..7
  const int q4 = lane & 3;           // 0..3
  const int mbase = wip * 16;

  // ---- Phase 1: pos-encoding GEMM via tf32 MMA; h1 += relu(enc) -----------
  {
    float acc[8][4];
    #pragma unroll
    for (int t8 = 0; t8 < 8; ++t8)
      #pragma unroll
      for (int j = 0; j < 4; ++j) acc[t8][j] = 0.0f;

    const float* geob = &s.u.geo[pt][0][0];
    #pragma unroll
    for (int ks = 0; ks < 2; ++ks) {
      const int r0 = (mbase + g4) * GS + ks * 8 + q4;
      const int r1 = r0 + 8 * GS;
      const float a0 = geob[r0],     a1v = geob[r1];
      const float a2f = geob[r0 + 4], a3v = geob[r1 + 4];
      uint32 ah0, al0, ah1, al1, ah2, al2, ah3, al3;
      split_tf32(a0,  ah0, al0);
      split_tf32(a1v, ah1, al1);
      split_tf32(a2f, ah2, al2);
      split_tf32(a3v, ah3, al3);
      #pragma unroll
      for (int t8 = 0; t8 < 8; ++t8) {
        const float b0 = s.WpT[ks * 8 + q4][t8 * 8 + g4];
        const float b1 = s.WpT[ks * 8 + q4 + 4][t8 * 8 + g4];
        uint32 bh0, bl0, bh1, bl1;
        split_tf32(b0, bh0, bl0);
        split_tf32(b1, bh1, bl1);
        mma_tf32(acc[t8], ah0, ah1, ah2, ah3, bh0, bh1);
        mma_tf32(acc[t8], ah0, ah1, ah2, ah3, bl0, bl1);
        mma_tf32(acc[t8], al0, al1, al2, al3, bh0, bh1);
      }
    }

    // h1[row][col] = feature + relu(enc) in-place (bias already inside acc)
    float* h1b = &s.h1[pt][0];
    #pragma unroll
    for (int t8 = 0; t8 < 8; ++t8) {
      const int n0 = t8 * 8 + 2 * q4;
      float2* p0 = reinterpret_cast<float2*>(&h1b[(mbase + g4) * H1S + n0]);
      float2* p1 = reinterpret_cast<float2*>(&h1b[(mbase + g4 + 8) * H1S + n0]);
      float2 f0 = *p0, f1 = *p1;
      f0.x += fmaxf(acc[t8][0], 0.0f);
      f0.y += fmaxf(acc[t8][1], 0.0f);
      f1.x += fmaxf(acc[t8][2], 0.0f);
      f1.y += fmaxf(acc[t8][3], 0.0f);
      *p0 = f0; *p1 = f1;
    }
  }
  __syncthreads();

  // ---- Phase 2: h2 GEMM via tf32 MMA (3-pass hi/lo) -----------------------
  {
    float acc[8][4];
    #pragma unroll
    for (int t8 = 0; t8 < 8; ++t8)
      #pragma unroll
      for (int j = 0; j < 4; ++j) acc[t8][j] = 0.0f;

    const float* h1b = &s.h1[pt][0];
    #pragma unroll
    for (int ks = 0; ks < 8; ++ks) {
      const int r0 = (mbase + g4) * H1S + ks * 8 + q4;
      const int r1 = r0 + 8 * H1S;
      const float a0 = h1b[r0],      a1v = h1b[r1];
      const float a2f = h1b[r0 + 4], a3v = h1b[r1 + 4];
      uint32 ah0, al0, ah1, al1, ah2, al2, ah3, al3;
      split_tf32(a0,  ah0, al0);
      split_tf32(a1v, ah1, al1);
      split_tf32(a2f, ah2, al2);
      split_tf32(a3v, ah3, al3);
      #pragma unroll
      for (int t8 = 0; t8 < 8; ++t8) {
        const float b0 = s.w.Wg2[ks * 8 + q4][t8 * 8 + g4];
        const float b1 = s.w.Wg2[ks * 8 + q4 + 4][t8 * 8 + g4];
        uint32 bh0, bl0, bh1, bl1;
        split_tf32(b0, bh0, bl0);
        split_tf32(b1, bh1, bl1);
        mma_tf32(acc[t8], ah0, ah1, ah2, ah3, bh0, bh1);
        mma_tf32(acc[t8], ah0, ah1, ah2, ah3, bl0, bl1);
        mma_tf32(acc[t8], al0, al1, al2, al3, bh0, bh1);
      }
    }

    // Epilogue: bias + ReLU, attention dot over k, max over k
    const float wv0 = s.Watt[mbase + g4];
    const float wv1 = s.Watt[mbase + g4 + 8];
    #pragma unroll
    for (int t8 = 0; t8 < 8; ++t8) {
      const int n0 = t8 * 8 + 2 * q4;
      const float b0 = s.bias2[n0], b1 = s.bias2[n0 + 1];
      const float h00 = fmaxf(acc[t8][0] + b0, 0.0f);
      const float h01 = fmaxf(acc[t8][1] + b1, 0.0f);
      const float h10 = fmaxf(acc[t8][2] + b0, 0.0f);
      const float h11 = fmaxf(acc[t8][3] + b1, 0.0f);
      float spa = h00 * wv0 + h10 * wv1;
      float spb = h01 * wv0 + h11 * wv1;
      float mpa = fmaxf(h00, h10);
      float mpb = fmaxf(h01, h11);
      #pragma unroll
      for (int m = 4; m <= 16; m <<= 1) {
        spa += __shfl_xor_sync(0xffffffffu, spa, m);
        spb += __shfl_xor_sync(0xffffffffu, spb, m);
        mpa = fmaxf(mpa, __shfl_xor_sync(0xffffffffu, mpa, m));
        mpb = fmaxf(mpb, __shfl_xor_sync(0xffffffffu, mpb, m));
      }
      if (g4 == 0) {
        *reinterpret_cast<float2*>(&s.u.t.ps[pt][wip][n0]) = make_float2(spa, spb);
        *reinterpret_cast<float2*>(&s.u.t.pm[pt][wip][n0]) = make_float2(mpa, mpb);
      }
    }
  }
  __syncthreads();   // Wg2 dead from here on

  // ---- Phase 3: wout fill (into Wg2 space) + softmax/pool/residual --------
  {
    float* wout = s.w.wout_raw;
    for (int i = tid; i < CCH * CCH; i += NTHREADS)
      wout[(i >> 6) * WOS + (i & 63)] = W_out[i];   // coalesced LDG + STS
  }
  {
    const int c = tp;
    const float sv = s.u.t.ps[pt][0][c] + s.u.t.ps[pt][1][c];  // b_att invariant
    const float mv = fmaxf(s.u.t.pm[pt][0][c], s.u.t.pm[pt][1][c]);

    float mx = sv;
    #pragma unroll
    for (int m = 16; m >= 1; m >>= 1)
      mx = fmaxf(mx, __shfl_xor_sync(0xffffffffu, mx, m));
    if ((tp & 31) == 0) s.u.t.redA[pt][wip] = mx;
    __syncthreads();
    mx = fmaxf(s.u.t.redA[pt][0], s.u.t.redA[pt][1]);

    const float e = expf(sv - mx);
    float se = e;
    #pragma unroll
    for (int m = 16; m >= 1; m >>= 1)
      se += __shfl_xor_sync(0xffffffffu, se, m);
    if ((tp & 31) == 0) s.u.t.redB[pt][wip] = se;
    __syncthreads();
    se = s.u.t.redB[pt][0] + s.u.t.redB[pt][1];

    const float score = e / se;
    s.u.t.resv[pt][c] = score * mv + features[base_pn * CCH + c];
  }
  __syncthreads();   // covers wout fill + resv

  // ---- Phase 4: out GEMM (f32x2, SMEM wout) + LayerNorm + ReLU ------------
  {
    const int o = tp;
    const float* wrow = &s.w.wout_raw[o * WOS];
    ull e2 = 0ULL;
    #pragma unroll
    for (int q = 0; q < 16; ++q) {
      ulonglong2 w = *reinterpret_cast<const ulonglong2*>(&wrow[q * 4]);
      ulonglong2 r = *reinterpret_cast<const ulonglong2*>(&s.u.t.resv[pt][q * 4]);
      fma2(e2, r.x, w.x);
      fma2(e2, r.y, w.y);
    }
    float2 ee = unpack2(e2);
    float acc = ee.x + ee.y + b_out[o];

    float sum = acc, sq = acc * acc;
    #pragma unroll
    for (int m = 16; m >= 1; m >>= 1) {
      sum += __shfl_xor_sync(0xffffffffu, sum, m);
      sq  += __shfl_xor_sync(0xffffffffu, sq, m);
    }
    if ((tp & 31) == 0) { s.u.t.redC[pt][wip] = sum; s.u.t.redD[pt][wip] = sq; }
    __syncthreads();
    sum = s.u.t.redC[pt][0] + s.u.t.redC[pt][1];
    sq  = s.u.t.redD[pt][0] + s.u.t.redD[pt][1];

    const float mu  = sum * (1.0f / 64.0f);
    const float var = sq * (1.0f / 64.0f) - mu * mu;
    const float r   = rsqrtf(var + EPSF);
    const float y   = ln_g[o] * (acc - mu) * r + ln_b[o];
    out[base_pn * CCH + o] = fmaxf(y, 0.0f);
  }
}

extern "C" void kernel_launch(void* const* d_in, const int* in_sizes, int n_in,
                              void* d_out, int out_size) {
  const float* points   = (const float*)d_in[0];
  const float* features = (const float*)d_in[1];
  const int*   gidx     = (const int*)  d_in[2];
  const float* W_pos    = (const float*)d_in[3];
  const float* b_pos    = (const float*)d_in[4];
  const float* bn1_g    = (const float*)d_in[5];
  const float* bn1_b    = (const float*)d_in[6];
  const float* bn1_m    = (const float*)d_in[7];
  const float* bn1_v    = (const float*)d_in[8];
  const float* W_gcm    = (const float*)d_in[9];
  const float* b_gcm    = (const float*)d_in[10];
  const float* bn2_g    = (const float*)d_in[11];
  const float* bn2_b    = (const float*)d_in[12];
  const float* bn2_m    = (const float*)d_in[13];
  const float* bn2_v    = (const float*)d_in[14];
  const float* W_att    = (const float*)d_in[15];
  // d_in[16] = b_att (scalar): softmax-invariant, unused.
  const float* W_out    = (const float*)d_in[17];
  const float* b_out    = (const float*)d_in[18];
  const float* ln_g     = (const float*)d_in[19];
  const float* ln_b     = (const float*)d_in[20];
  float* out = (float*)d_out;

  const size_t smem = sizeof(Smem);
  cudaFuncSetAttribute((const void*)bridgenet_kernel,
                       cudaFuncAttributeMaxDynamicSharedMemorySize, (int)smem);

  const int total_pts = 2 * NPTS;             // 32768
  dim3 grid(total_pts / PPB);                 // 8192 blocks
  bridgenet_kernel<<<grid, NTHREADS, smem>>>(
      points, features, gidx, W_pos, b_pos,
      bn1_g, bn1_b, bn1_m, bn1_v,
      W_gcm, b_gcm, bn2_g, bn2_b, bn2_m, bn2_v,
      W_att, W_out, b_out, ln_g, ln_b, out);
}

// round 13
// speedup vs baseline: 1.7577x; 1.0143x over previous
#include <cuda_runtime.h>
#include <math.h>

typedef unsigned long long ull;
typedef unsigned int uint32;

#define NPTS 16384
#define KNB 32
#define CCH 64
#define PPB 4          // points per block
#define NTHREADS 256
#define H1S 68         // h1 row stride: conflict-free fragments
#define WGS 72         // Wg2 row stride: conflict-free B fragments
#define WPS 72         // WpT row stride
#define GS  20         // geo row stride: conflict-free A fragments
#define WOS 68         // woutT row stride (c-major): conflict-free lane loads
#define EPSF 1e-5f

// ---- tf32 MMA: D += A(16x8) * B(8x8), fp32 accumulate ----
__device__ __forceinline__ void mma_tf32(float* d,
    uint32 a0, uint32 a1, uint32 a2, uint32 a3, uint32 b0, uint32 b1) {
  asm("mma.sync.aligned.m16n8k8.row.col.f32.tf32.tf32.f32 "
      "{%0,%1,%2,%3}, {%4,%5,%6,%7}, {%8,%9}, {%0,%1,%2,%3};"
      : "+f"(d[0]), "+f"(d[1]), "+f"(d[2]), "+f"(d[3])
      : "r"(a0), "r"(a1), "r"(a2), "r"(a3), "r"(b0), "r"(b1));
}
__device__ __forceinline__ void split_tf32(float x, uint32& hi, uint32& lo) {
  hi = __float_as_uint(x) & 0xFFFFE000u;
  lo = __float_as_uint(x - __uint_as_float(hi));
}
// named barrier: 2 warps of one point
__device__ __forceinline__ void bar_pt(int id) {
  asm volatile("bar.sync %0, 64;" :: "r"(id) : "memory");
}

struct Smem {
  float WpT[16][WPS];            // [g][c]: rows 0-9 = a1*W_pos^T, row 10 = bias1, rest 0
  union {                        // Wg2 (phases 1-2) then woutT (phases 3-4)
    float Wg2[CCH][WGS];         // [c][d] = a2[d]*W_gcm[d][c]
    float woutT_raw[CCH * WGS];  // woutT[c*WOS + o] = W_out[o][c]
  } w;
  float a1s[CCH], a2s[CCH], bias1a[CCH], bias2[CCH];
  float Watt[KNB];
  int   nidx[PPB][KNB];
  float h1[PPB][KNB * H1S];
  float geo[PPB][KNB][GS];       // NOT unioned: points skew freely
  struct {
    float ps[PPB][2][CCH];
    float pm[PPB][2][CCH];
    float resv[PPB][CCH];
    float redC[PPB][2], redD[PPB][2];
  } t;
};

__global__ __launch_bounds__(NTHREADS, 3)
void bridgenet_kernel(
    const float* __restrict__ points,
    const float* __restrict__ features,
    const int*   __restrict__ gidx,
    const float* __restrict__ W_pos,
    const float* __restrict__ b_pos,
    const float* __restrict__ bn1_g, const float* __restrict__ bn1_b,
    const float* __restrict__ bn1_m, const float* __restrict__ bn1_v,
    const float* __restrict__ W_gcm,
    const float* __restrict__ b_gcm,
    const float* __restrict__ bn2_g, const float* __restrict__ bn2_b,
    const float* __restrict__ bn2_m, const float* __restrict__ bn2_v,
    const float* __restrict__ W_att,
    const float* __restrict__ W_out,
    const float* __restrict__ b_out,
    const float* __restrict__ ln_g, const float* __restrict__ ln_b,
    float* __restrict__ out)
{
  extern __shared__ char smem_raw[];
  Smem& s = *reinterpret_cast<Smem*>(smem_raw);
  const int tid = threadIdx.x;

  const int pt = tid >> 6;           // point within block
  const int tp = tid & 63;           // thread within point
  const int wip = tp >> 5;           // warp within point
  const int p  = blockIdx.x * PPB + pt;
  const int bb = p >> 14;            // N = 16384
  const int nn = p & (NPTS - 1);
  const int base_pn = bb * NPTS + nn;

  // ---- Phase 0: BN folding + neighbor idx + geo staging -------------------
  if (tid < CCH) {
    float a1 = bn1_g[tid] * rsqrtf(bn1_v[tid] + EPSF);
    s.a1s[tid] = a1;
    s.bias1a[tid] = a1 * (b_pos[tid] - bn1_m[tid]) + bn1_b[tid];
    float a2 = bn2_g[tid] * rsqrtf(bn2_v[tid] + EPSF);
    s.a2s[tid] = a2;
    s.bias2[tid] = a2 * (b_gcm[tid] - bn2_m[tid]) + bn2_b[tid];
  }
  if (tid >= CCH && tid < CCH + KNB) s.Watt[tid - CCH] = W_att[tid - CCH];

  if (tp < KNB) {                    // one thread per (pt, neighbor)
    const int idx = gidx[base_pn * KNB + tp];
    s.nidx[pt][tp] = idx;
    const int gb = bb * NPTS + idx;
    const float xix = points[base_pn * 3 + 0];
    const float xiy = points[base_pn * 3 + 1];
    const float xiz = points[base_pn * 3 + 2];
    const float gx = points[gb * 3 + 0];
    const float gy = points[gb * 3 + 1];
    const float gz = points[gb * 3 + 2];
    const float dx = xix - gx, dy = xiy - gy, dz = xiz - gz;
    const float dist = sqrtf(dx*dx + dy*dy + dz*dz);
    float* gr = &s.geo[pt][tp][0];
    gr[0] = xix; gr[1] = xiy; gr[2] = xiz;
    gr[3] = gx;  gr[4] = gy;  gr[5] = gz;
    gr[6] = dx;  gr[7] = dy;  gr[8] = dz;
    gr[9] = dist; gr[10] = 1.0f;               // pairs with bias row of WpT
    gr[11] = 0.0f; gr[12] = 0.0f; gr[13] = 0.0f; gr[14] = 0.0f; gr[15] = 0.0f;
  }
  __syncthreads();                   // sync1: consts + nidx + geo published

  // ---- Weight scatter + line-contiguous feature gather into h1 ------------
  for (int i = tid; i < 16 * CCH; i += NTHREADS) {
    const int g = i >> 6, c = i & 63;
    float v = 0.0f;
    if (g < 10)       v = s.a1s[c] * W_pos[c * 10 + g];
    else if (g == 10) v = s.bias1a[c];
    s.WpT[g][c] = v;
  }
  for (int i = tid; i < CCH * CCH; i += NTHREADS) {
    const int d = i >> 6, c = i & 63;
    s.w.Wg2[c][d] = s.a2s[d] * W_gcm[i];      // W_gcm[d][c]
  }
  {
    const int chunk = tp & 15;                // 16B chunk within feature row
    const int rsub  = tp >> 4;                // 0..3
    #pragma unroll
    for (int j = 0; j < 8; ++j) {
      const int row = rsub + 4 * j;           // neighbor 0..31
      const int gb  = bb * NPTS + s.nidx[pt][row];
      const float4 v = *reinterpret_cast<const float4*>(features + gb * CCH + chunk * 4);
      *reinterpret_cast<float4*>(&s.h1[pt][row * H1S + chunk * 4]) = v;
    }
  }
  __syncthreads();                   // sync2: weights + gathered features + geo ready

  const int lane = tp & 31;
  const int g4 = lane >> 2;          // 0..7
  const int q4 = lane & 3;           // 0..3
  const int mbase = wip * 16;

  // ---- Phase 1: pos-encoding GEMM via tf32 MMA; h1 += relu(enc) -----------
  {
    float acc[8][4];
    #pragma unroll
    for (int t8 = 0; t8 < 8; ++t8)
      #pragma unroll
      for (int j = 0; j < 4; ++j) acc[t8][j] = 0.0f;

    const float* geob = &s.geo[pt][0][0];
    #pragma unroll
    for (int ks = 0; ks < 2; ++ks) {
      const int r0 = (mbase + g4) * GS + ks * 8 + q4;
      const int r1 = r0 + 8 * GS;
      const float a0 = geob[r0],      a1v = geob[r1];
      const float a2f = geob[r0 + 4], a3v = geob[r1 + 4];
      uint32 ah0, al0, ah1, al1, ah2, al2, ah3, al3;
      split_tf32(a0,  ah0, al0);
      split_tf32(a1v, ah1, al1);
      split_tf32(a2f, ah2, al2);
      split_tf32(a3v, ah3, al3);
      #pragma unroll
      for (int t8 = 0; t8 < 8; ++t8) {
        const float b0 = s.WpT[ks * 8 + q4][t8 * 8 + g4];
        const float b1 = s.WpT[ks * 8 + q4 + 4][t8 * 8 + g4];
        uint32 bh0, bl0, bh1, bl1;
        split_tf32(b0, bh0, bl0);
        split_tf32(b1, bh1, bl1);
        mma_tf32(acc[t8], ah0, ah1, ah2, ah3, bh0, bh1);
        mma_tf32(acc[t8], ah0, ah1, ah2, ah3, bl0, bl1);
        mma_tf32(acc[t8], al0, al1, al2, al3, bh0, bh1);
      }
    }

    // h1[row][col] = feature + relu(enc): rows are this warp's OWN rows
    float* h1b = &s.h1[pt][0];
    #pragma unroll
    for (int t8 = 0; t8 < 8; ++t8) {
      const int n0 = t8 * 8 + 2 * q4;
      float2* p0 = reinterpret_cast<float2*>(&h1b[(mbase + g4) * H1S + n0]);
      float2* p1 = reinterpret_cast<float2*>(&h1b[(mbase + g4 + 8) * H1S + n0]);
      float2 f0 = *p0, f1 = *p1;
      f0.x += fmaxf(acc[t8][0], 0.0f);
      f0.y += fmaxf(acc[t8][1], 0.0f);
      f1.x += fmaxf(acc[t8][2], 0.0f);
      f1.y += fmaxf(acc[t8][3], 0.0f);
      *p0 = f0; *p1 = f1;
    }
  }
  __syncwarp();                      // phase1->2: own-warp rows only

  // ---- Phase 2: h2 GEMM via tf32 MMA (3-pass hi/lo) -----------------------
  {
    float acc[8][4];
    #pragma unroll
    for (int t8 = 0; t8 < 8; ++t8)
      #pragma unroll
      for (int j = 0; j < 4; ++j) acc[t8][j] = 0.0f;

    const float* h1b = &s.h1[pt][0];
    #pragma unroll
    for (int ks = 0; ks < 8; ++ks) {
      const int r0 = (mbase + g4) * H1S + ks * 8 + q4;
      const int r1 = r0 + 8 * H1S;
      const float a0 = h1b[r0],      a1v = h1b[r1];
      const float a2f = h1b[r0 + 4], a3v = h1b[r1 + 4];
      uint32 ah0, al0, ah1, al1, ah2, al2, ah3, al3;
      split_tf32(a0,  ah0, al0);
      split_tf32(a1v, ah1, al1);
      split_tf32(a2f, ah2, al2);
      split_tf32(a3v, ah3, al3);
      #pragma unroll
      for (int t8 = 0; t8 < 8; ++t8) {
        const float b0 = s.w.Wg2[ks * 8 + q4][t8 * 8 + g4];
        const float b1 = s.w.Wg2[ks * 8 + q4 + 4][t8 * 8 + g4];
        uint32 bh0, bl0, bh1, bl1;
        split_tf32(b0, bh0, bl0);
        split_tf32(b1, bh1, bl1);
        mma_tf32(acc[t8], ah0, ah1, ah2, ah3, bh0, bh1);
        mma_tf32(acc[t8], ah0, ah1, ah2, ah3, bl0, bl1);
        mma_tf32(acc[t8], al0, al1, al2, al3, bh0, bh1);
      }
    }

    // Epilogue: bias + ReLU, attention dot over k, max over k
    const float wv0 = s.Watt[mbase + g4];
    const float wv1 = s.Watt[mbase + g4 + 8];
    #pragma unroll
    for (int t8 = 0; t8 < 8; ++t8) {
      const int n0 = t8 * 8 + 2 * q4;
      const float b0 = s.bias2[n0], b1 = s.bias2[n0 + 1];
      const float h00 = fmaxf(acc[t8][0] + b0, 0.0f);
      const float h01 = fmaxf(acc[t8][1] + b1, 0.0f);
      const float h10 = fmaxf(acc[t8][2] + b0, 0.0f);
      const float h11 = fmaxf(acc[t8][3] + b1, 0.0f);
      float spa = h00 * wv0 + h10 * wv1;
      float spb = h01 * wv0 + h11 * wv1;
      float mpa = fmaxf(h00, h10);
      float mpb = fmaxf(h01, h11);
      #pragma unroll
      for (int m = 4; m <= 16; m <<= 1) {
        spa += __shfl_xor_sync(0xffffffffu, spa, m);
        spb += __shfl_xor_sync(0xffffffffu, spb, m);
        mpa = fmaxf(mpa, __shfl_xor_sync(0xffffffffu, mpa, m));
        mpb = fmaxf(mpb, __shfl_xor_sync(0xffffffffu, mpb, m));
      }
      if (g4 == 0) {
        *reinterpret_cast<float2*>(&s.t.ps[pt][wip][n0]) = make_float2(spa, spb);
        *reinterpret_cast<float2*>(&s.t.pm[pt][wip][n0]) = make_float2(mpa, mpb);
      }
    }
  }
  __syncthreads();                   // sync3: all phase-2 done; Wg2 dead; ps/pm ready

  // ---- Phase 3: woutT fill + per-warp full softmax/pool/residual ----------
  const int o = tp;
  const float bo = b_out[o];                   // prefetch phase-4 params
  const float lg = ln_g[o];
  const float lb = ln_b[o];
  {
    float* wt = s.w.woutT_raw;                 // transposed fill: woutT[c][o]
    for (int i = tid; i < CCH * CCH; i += NTHREADS)
      wt[(i & 63) * WOS + (i >> 6)] = W_out[i];
  }
  {
    const int c0 = lane, c1 = lane + 32;
    const float f_res = features[base_pn * CCH + o];   // residual, coalesced
    float sv0 = s.t.ps[pt][0][c0] + s.t.ps[pt][1][c0]; // b_att softmax-invariant
    float sv1 = s.t.ps[pt][0][c1] + s.t.ps[pt][1][c1];
    float mv0 = fmaxf(s.t.pm[pt][0][c0], s.t.pm[pt][1][c0]);
    float mv1 = fmaxf(s.t.pm[pt][0][c1], s.t.pm[pt][1][c1]);

    float mx = fmaxf(sv0, sv1);                // full 64-channel max, intra-warp
    #pragma unroll
    for (int m = 16; m >= 1; m >>= 1)
      mx = fmaxf(mx, __shfl_xor_sync(0xffffffffu, mx, m));

    const float e0 = expf(sv0 - mx);
    const float e1 = expf(sv1 - mx);
    float se = e0 + e1;
    #pragma unroll
    for (int m = 16; m >= 1; m >>= 1)
      se += __shfl_xor_sync(0xffffffffu, se, m);

    const float ec = wip ? e1 : e0;            // channel o = lane + 32*wip
    const float mc = wip ? mv1 : mv0;
    s.t.resv[pt][o] = (ec / se) * mc + f_res;
  }
  __syncthreads();                   // sync4: woutT + resv published

  // ---- Phase 4: out GEMM (conflict-free) + LayerNorm + ReLU ---------------
  {
    const float* wt = s.w.woutT_raw;
    float acc = bo;
    #pragma unroll
    for (int c4 = 0; c4 < 16; ++c4) {
      const float4 rv = *reinterpret_cast<const float4*>(&s.t.resv[pt][c4 * 4]);
      acc = fmaf(rv.x, wt[(c4 * 4 + 0) * WOS + o], acc);
      acc = fmaf(rv.y, wt[(c4 * 4 + 1) * WOS + o], acc);
      acc = fmaf(rv.z, wt[(c4 * 4 + 2) * WOS + o], acc);
      acc = fmaf(rv.w, wt[(c4 * 4 + 3) * WOS + o], acc);
    }

    float sum = acc, sq = acc * acc;
    #pragma unroll
    for (int m = 16; m >= 1; m >>= 1) {
      sum += __shfl_xor_sync(0xffffffffu, sum, m);
      sq  += __shfl_xor_sync(0xffffffffu, sq, m);
    }
    if (lane == 0) { s.t.redC[pt][wip] = sum; s.t.redD[pt][wip] = sq; }
    bar_pt(1 + pt);                  // point-local exchange
    sum = s.t.redC[pt][0] + s.t.redC[pt][1];
    sq  = s.t.redD[pt][0] + s.t.redD[pt][1];

    const float mu  = sum * (1.0f / 64.0f);
    const float var = sq * (1.0f / 64.0f) - mu * mu;
    const float r   = rsqrtf(var + EPSF);
    const float y   = lg * (acc - mu) * r + lb;
    out[base_pn * CCH + o] = fmaxf(y, 0.0f);
  }
}

extern "C" void kernel_launch(void* const* d_in, const int* in_sizes, int n_in,
                              void* d_out, int out_size) {
  const float* points   = (const float*)d_in[0];
  const float* features = (const float*)d_in[1];
  const int*   gidx     = (const int*)  d_in[2];
  const float* W_pos    = (const float*)d_in[3];
  const float* b_pos    = (const float*)d_in[4];
  const float* bn1_g    = (const float*)d_in[5];
  const float* bn1_b    = (const float*)d_in[6];
  const float* bn1_m    = (const float*)d_in[7];
  const float* bn1_v    = (const float*)d_in[8];
  const float* W_gcm    = (const float*)d_in[9];
  const float* b_gcm    = (const float*)d_in[10];
  const float* bn2_g    = (const float*)d_in[11];
  const float* bn2_b    = (const float*)d_in[12];
  const float* bn2_m    = (const float*)d_in[13];
  const float* bn2_v    = (const float*)d_in[14];
  const float* W_att    = (const float*)d_in[15];
  // d_in[16] = b_att (scalar): softmax-invariant, unused.
  const float* W_out    = (const float*)d_in[17];
  const float* b_out    = (const float*)d_in[18];
  const float* ln_g     = (const float*)d_in[19];
  const float* ln_b     = (const float*)d_in[20];
  float* out = (float*)d_out;

  const size_t smem = sizeof(Smem);
  cudaFuncSetAttribute((const void*)bridgenet_kernel,
                       cudaFuncAttributeMaxDynamicSharedMemorySize, (int)smem);

  const int total_pts = 2 * NPTS;             // 32768
  dim3 grid(total_pts / PPB);                 // 8192 blocks
  bridgenet_kernel<<<grid, NTHREADS, smem>>>(
      points, features, gidx, W_pos, b_pos,
      bn1_g, bn1_b, bn1_m, bn1_v,
      W_gcm, b_gcm, bn2_g, bn2_b, bn2_m, bn2_v,
      W_att, W_out, b_out, ln_g, ln_b, out);
}